// round 4
// baseline (speedup 1.0000x reference)
#include <cuda_runtime.h>
#include <math.h>

// Problem constants (B=4, T=4096, C=512)
#define BATCH 4
#define SEQ   4096
#define DM    512
#define DM3   1536

// GEMM tiling
#define BM 128
#define BN 128
#define BK 16
#define TM 8
#define TN 8
#define NTHREADS 256

// Scratch: __device__ globals (no allocations allowed in kernel_launch)
__device__ float g_qkv[(size_t)BATCH * SEQ * DM3];      // ~100 MB
__device__ float g_scores[(size_t)BATCH * SEQ * SEQ];   // ~268 MB
__device__ float g_att[(size_t)BATCH * SEQ * DM];       // ~34 MB

// ---------------------------------------------------------------------------
// C[M,N] = A[M,K] * B[N,K]^T   (both row-major, "nt" form: x @ W^T)
// All dims divisible by tile sizes -> no guards.
// ---------------------------------------------------------------------------
__global__ __launch_bounds__(NTHREADS)
void sgemm_nt_kernel(const float* __restrict__ A, int lda,
                     const float* __restrict__ B, int ldb,
                     float* __restrict__ C, int ldc, int K)
{
    __shared__ float As[BK][BM + 4];
    __shared__ float Bs[BK][BN + 4];

    const int tid = threadIdx.x;
    const int tx = tid & 15;       // 0..15 -> N direction
    const int ty = tid >> 4;       // 0..15 -> M direction
    const int m0 = blockIdx.y * BM;
    const int n0 = blockIdx.x * BN;

    float acc[TM][TN];
#pragma unroll
    for (int i = 0; i < TM; i++)
#pragma unroll
        for (int j = 0; j < TN; j++) acc[i][j] = 0.0f;

    for (int k0 = 0; k0 < K; k0 += BK) {
        // Load A tile (128 x 16) transposed into As[k][m]
#pragma unroll
        for (int it = 0; it < 2; ++it) {
            int idx = it * 256 + tid;
            int m = idx >> 2;
            int kc = (idx & 3) << 2;
            float4 v = *reinterpret_cast<const float4*>(
                &A[(size_t)(m0 + m) * lda + k0 + kc]);
            As[kc + 0][m] = v.x; As[kc + 1][m] = v.y;
            As[kc + 2][m] = v.z; As[kc + 3][m] = v.w;
        }
        // Load B tile (128 x 16) transposed into Bs[k][n]
#pragma unroll
        for (int it = 0; it < 2; ++it) {
            int idx = it * 256 + tid;
            int n = idx >> 2;
            int kc = (idx & 3) << 2;
            float4 v = *reinterpret_cast<const float4*>(
                &B[(size_t)(n0 + n) * ldb + k0 + kc]);
            Bs[kc + 0][n] = v.x; Bs[kc + 1][n] = v.y;
            Bs[kc + 2][n] = v.z; Bs[kc + 3][n] = v.w;
        }
        __syncthreads();
#pragma unroll
        for (int k = 0; k < BK; k++) {
            float a[TM], b[TN];
#pragma unroll
            for (int i = 0; i < TM; i++) a[i] = As[k][ty * TM + i];
#pragma unroll
            for (int j = 0; j < TN; j++) b[j] = Bs[k][tx * TN + j];
#pragma unroll
            for (int i = 0; i < TM; i++)
#pragma unroll
                for (int j = 0; j < TN; j++) acc[i][j] += a[i] * b[j];
        }
        __syncthreads();
    }

#pragma unroll
    for (int i = 0; i < TM; i++) {
        int row = m0 + ty * TM + i;
        float4* cp = reinterpret_cast<float4*>(
            &C[(size_t)row * ldc + n0 + tx * TN]);
        float4 v0 = make_float4(acc[i][0], acc[i][1], acc[i][2], acc[i][3]);
        float4 v1 = make_float4(acc[i][4], acc[i][5], acc[i][6], acc[i][7]);
        cp[0] = v0; cp[1] = v1;
    }
}

// ---------------------------------------------------------------------------
// Causal QK^T: S[b,t,s] = scale * sum_c Q[b,t,c]*K[b,s,c], masked to -inf for s>t.
// Tiles fully above the diagonal just write -inf (no compute).
// ---------------------------------------------------------------------------
__global__ __launch_bounds__(NTHREADS)
void qk_kernel(const float* __restrict__ qkv, float* __restrict__ S, float scale)
{
    const int b = blockIdx.z;
    const int m0 = blockIdx.y * BM;   // query tile
    const int n0 = blockIdx.x * BN;   // key tile
    const int tid = threadIdx.x;
    const int tx = tid & 15;
    const int ty = tid >> 4;

    float* Sb = S + (size_t)b * SEQ * SEQ;

    if (n0 > m0) {   // entire tile above diagonal -> -inf, no compute
        const float4 ninf = make_float4(-INFINITY, -INFINITY, -INFINITY, -INFINITY);
#pragma unroll
        for (int i = 0; i < TM; i++) {
            int row = m0 + ty * TM + i;
            float4* cp = reinterpret_cast<float4*>(
                &Sb[(size_t)row * SEQ + n0 + tx * TN]);
            cp[0] = ninf; cp[1] = ninf;
        }
        return;
    }

    const float* Q  = qkv + (size_t)b * SEQ * DM3;         // lda = DM3
    const float* Kp = qkv + (size_t)b * SEQ * DM3 + DM;    // keys

    __shared__ float As[BK][BM + 4];
    __shared__ float Bs[BK][BN + 4];

    float acc[TM][TN];
#pragma unroll
    for (int i = 0; i < TM; i++)
#pragma unroll
        for (int j = 0; j < TN; j++) acc[i][j] = 0.0f;

    for (int k0 = 0; k0 < DM; k0 += BK) {
#pragma unroll
        for (int it = 0; it < 2; ++it) {
            int idx = it * 256 + tid;
            int m = idx >> 2;
            int kc = (idx & 3) << 2;
            float4 v = *reinterpret_cast<const float4*>(
                &Q[(size_t)(m0 + m) * DM3 + k0 + kc]);
            As[kc + 0][m] = v.x; As[kc + 1][m] = v.y;
            As[kc + 2][m] = v.z; As[kc + 3][m] = v.w;
        }
#pragma unroll
        for (int it = 0; it < 2; ++it) {
            int idx = it * 256 + tid;
            int n = idx >> 2;
            int kc = (idx & 3) << 2;
            float4 v = *reinterpret_cast<const float4*>(
                &Kp[(size_t)(n0 + n) * DM3 + k0 + kc]);
            Bs[kc + 0][n] = v.x; Bs[kc + 1][n] = v.y;
            Bs[kc + 2][n] = v.z; Bs[kc + 3][n] = v.w;
        }
        __syncthreads();
#pragma unroll
        for (int k = 0; k < BK; k++) {
            float a[TM], bb[TN];
#pragma unroll
            for (int i = 0; i < TM; i++) a[i] = As[k][ty * TM + i];
#pragma unroll
            for (int j = 0; j < TN; j++) bb[j] = Bs[k][tx * TN + j];
#pragma unroll
            for (int i = 0; i < TM; i++)
#pragma unroll
                for (int j = 0; j < TN; j++) acc[i][j] += a[i] * bb[j];
        }
        __syncthreads();
    }

    const bool diag = (m0 == n0);
#pragma unroll
    for (int i = 0; i < TM; i++) {
        int row = m0 + ty * TM + i;
        float o[TN];
#pragma unroll
        for (int j = 0; j < TN; j++) {
            int col = n0 + tx * TN + j;
            float v = acc[i][j] * scale;
            if (diag && col > row) v = -INFINITY;
            o[j] = v;
        }
        float4* cp = reinterpret_cast<float4*>(
            &Sb[(size_t)row * SEQ + n0 + tx * TN]);
        cp[0] = make_float4(o[0], o[1], o[2], o[3]);
        cp[1] = make_float4(o[4], o[5], o[6], o[7]);
    }
}

// ---------------------------------------------------------------------------
// Row softmax over [B*T, T], in-place. One block per row, 256 thr x 16 elems.
// exp(-inf - m) = 0, so masked entries become exact zeros.
// ---------------------------------------------------------------------------
__global__ __launch_bounds__(256)
void softmax_kernel(float* __restrict__ S)
{
    const size_t row = blockIdx.x;
    float* p = S + row * (size_t)SEQ;
    const int tid = threadIdx.x;

    float v[16];
#pragma unroll
    for (int i = 0; i < 16; i++) v[i] = p[tid + (i << 8)];

    float m = -INFINITY;
#pragma unroll
    for (int i = 0; i < 16; i++) m = fmaxf(m, v[i]);
#pragma unroll
    for (int o = 16; o > 0; o >>= 1)
        m = fmaxf(m, __shfl_xor_sync(0xffffffffu, m, o));

    __shared__ float redm[8], reds[8];
    if ((tid & 31) == 0) redm[tid >> 5] = m;
    __syncthreads();
    m = fmaxf(fmaxf(fmaxf(redm[0], redm[1]), fmaxf(redm[2], redm[3])),
              fmaxf(fmaxf(redm[4], redm[5]), fmaxf(redm[6], redm[7])));

    float s = 0.0f;
#pragma unroll
    for (int i = 0; i < 16; i++) { v[i] = expf(v[i] - m); s += v[i]; }
#pragma unroll
    for (int o = 16; o > 0; o >>= 1)
        s += __shfl_xor_sync(0xffffffffu, s, o);
    if ((tid & 31) == 0) reds[tid >> 5] = s;
    __syncthreads();
    s = reds[0] + reds[1] + reds[2] + reds[3] +
        reds[4] + reds[5] + reds[6] + reds[7];

    const float inv = 1.0f / s;
#pragma unroll
    for (int i = 0; i < 16; i++) p[tid + (i << 8)] = v[i] * inv;
}

// ---------------------------------------------------------------------------
// O[b,t,c] = sum_s P[b,t,s] * V[b,s,c]   (A@B form; B is [K,N] row-major)
// Causal: P[t,s]==0 for s>t -> truncate K loop at row-tile end.
// ---------------------------------------------------------------------------
__global__ __launch_bounds__(NTHREADS)
void pv_kernel(const float* __restrict__ S, const float* __restrict__ qkv,
               float* __restrict__ O)
{
    const int b = blockIdx.z;
    const int m0 = blockIdx.y * BM;
    const int n0 = blockIdx.x * BN;
    const int tid = threadIdx.x;
    const int tx = tid & 15;
    const int ty = tid >> 4;

    const float* A  = S + (size_t)b * SEQ * SEQ;                 // lda = SEQ
    const float* Bv = qkv + (size_t)b * SEQ * DM3 + 2 * DM;      // V, ldb = DM3
    float* Ob = O + (size_t)b * SEQ * DM;

    __shared__ float As[BK][BM + 4];
    __shared__ float Bs[BK][BN + 4];

    float acc[TM][TN];
#pragma unroll
    for (int i = 0; i < TM; i++)
#pragma unroll
        for (int j = 0; j < TN; j++) acc[i][j] = 0.0f;

    const int kend = m0 + BM;    // causal truncation (kend <= SEQ)

    for (int k0 = 0; k0 < kend; k0 += BK) {
#pragma unroll
        for (int it = 0; it < 2; ++it) {
            int idx = it * 256 + tid;
            int m = idx >> 2;
            int kc = (idx & 3) << 2;
            float4 v = *reinterpret_cast<const float4*>(
                &A[(size_t)(m0 + m) * SEQ + k0 + kc]);
            As[kc + 0][m] = v.x; As[kc + 1][m] = v.y;
            As[kc + 2][m] = v.z; As[kc + 3][m] = v.w;
        }
        // B tile: 16 (k) x 128 (n), direct layout
#pragma unroll
        for (int it = 0; it < 2; ++it) {
            int idx = it * 256 + tid;
            int k = idx >> 5;
            int nc = (idx & 31) << 2;
            float4 v = *reinterpret_cast<const float4*>(
                &Bv[(size_t)(k0 + k) * DM3 + n0 + nc]);
            *reinterpret_cast<float4*>(&Bs[k][nc]) = v;
        }
        __syncthreads();
#pragma unroll
        for (int k = 0; k < BK; k++) {
            float a[TM], bb[TN];
#pragma unroll
            for (int i = 0; i < TM; i++) a[i] = As[k][ty * TM + i];
#pragma unroll
            for (int j = 0; j < TN; j++) bb[j] = Bs[k][tx * TN + j];
#pragma unroll
            for (int i = 0; i < TM; i++)
#pragma unroll
                for (int j = 0; j < TN; j++) acc[i][j] += a[i] * bb[j];
        }
        __syncthreads();
    }

#pragma unroll
    for (int i = 0; i < TM; i++) {
        int row = m0 + ty * TM + i;
        float4* cp = reinterpret_cast<float4*>(
            &Ob[(size_t)row * DM + n0 + tx * TN]);
        cp[0] = make_float4(acc[i][0], acc[i][1], acc[i][2], acc[i][3]);
        cp[1] = make_float4(acc[i][4], acc[i][5], acc[i][6], acc[i][7]);
    }
}

// ---------------------------------------------------------------------------
extern "C" void kernel_launch(void* const* d_in, const int* in_sizes, int n_in,
                              void* d_out, int out_size)
{
    const float* x      = (const float*)d_in[0];   // [B,T,C]
    const float* w_qkv  = (const float*)d_in[1];   // [3C,C]
    const float* w_proj = (const float*)d_in[2];   // [C,C]
    float* out = (float*)d_out;                    // [B,T,C]

    float *qkv, *scores, *att;
    cudaGetSymbolAddress((void**)&qkv,    g_qkv);
    cudaGetSymbolAddress((void**)&scores, g_scores);
    cudaGetSymbolAddress((void**)&att,    g_att);

    const float scale = 1.0f / sqrtf((float)DM);
    dim3 blk(NTHREADS);

    // 1) qkv = x @ w_qkv^T   [16384 x 1536 x 512]
    sgemm_nt_kernel<<<dim3(DM3 / BN, (BATCH * SEQ) / BM), blk>>>(
        x, DM, w_qkv, DM, qkv, DM3, DM);

    // 2) scores = causal(Q @ K^T * scale)
    qk_kernel<<<dim3(SEQ / BN, SEQ / BM, BATCH), blk>>>(qkv, scores, scale);

    // 3) row softmax in-place
    softmax_kernel<<<BATCH * SEQ, 256>>>(scores);

    // 4) att = P @ V  (causal-truncated K loop)
    pv_kernel<<<dim3(DM / BN, SEQ / BM, BATCH), blk>>>(scores, qkv, att);

    // 5) out = att @ w_proj^T
    sgemm_nt_kernel<<<dim3(DM / BN, (BATCH * SEQ) / BM), blk>>>(
        att, DM, w_proj, DM, out, DM, DM);
}

// round 6
// speedup vs baseline: 2.2696x; 2.2696x over previous
#include <cuda_runtime.h>
#include <cuda_bf16.h>
#include <cstdint>
#include <math.h>

// Problem constants (B=4, T=4096, C=512)
#define BATCH 4
#define SEQ   4096
#define DM    512
#define DM3   1536

// ---------------------------------------------------------------------------
// Scratch (device globals; no allocation allowed)
// ---------------------------------------------------------------------------
#define NX   ((size_t)BATCH * SEQ * DM)
#define NQKV ((size_t)BATCH * SEQ * DM3)
#define NS   ((size_t)BATCH * SEQ * SEQ)

__device__ __nv_bfloat16 g_xhi[NX],   g_xlo[NX];
__device__ __nv_bfloat16 g_wqhi[(size_t)DM3 * DM], g_wqlo[(size_t)DM3 * DM];
__device__ __nv_bfloat16 g_wphi[(size_t)DM * DM],  g_wplo[(size_t)DM * DM];
__device__ __nv_bfloat16 g_qkvhi[NQKV], g_qkvlo[NQKV];
__device__ float         g_scores[NS];
__device__ __nv_bfloat16 g_phi[NS], g_plo[NS];
__device__ __nv_bfloat16 g_vthi[NX], g_vtlo[NX];
__device__ __nv_bfloat16 g_atthi[NX], g_attlo[NX];

// ---------------------------------------------------------------------------
// Small PTX helpers
// ---------------------------------------------------------------------------
__device__ __forceinline__ uint32_t smem_to_u32(const void* p) {
    uint32_t a;
    asm("{ .reg .u64 t; cvta.to.shared.u64 t, %1; cvt.u32.u64 %0, t; }"
        : "=r"(a) : "l"(p));
    return a;
}
__device__ __forceinline__ uint32_t lds_u32(uint32_t a) {
    uint32_t v;
    asm volatile("ld.shared.b32 %0, [%1];" : "=r"(v) : "r"(a));
    return v;
}
#define CP_ASYNC16(dst, src) \
    asm volatile("cp.async.ca.shared.global [%0], [%1], 16;" :: "r"(dst), "l"(src))
#define CP_COMMIT() asm volatile("cp.async.commit_group;" ::: "memory")
#define CP_WAIT(n)  asm volatile("cp.async.wait_group %0;" :: "n"(n) : "memory")

__device__ __forceinline__ void mma16816(float* c,
        uint32_t a0, uint32_t a1, uint32_t a2, uint32_t a3,
        uint32_t b0, uint32_t b1) {
    asm volatile(
        "mma.sync.aligned.m16n8k16.row.col.f32.bf16.bf16.f32 "
        "{%0,%1,%2,%3}, {%4,%5,%6,%7}, {%8,%9}, {%0,%1,%2,%3};"
        : "+f"(c[0]), "+f"(c[1]), "+f"(c[2]), "+f"(c[3])
        : "r"(a0), "r"(a1), "r"(a2), "r"(a3), "r"(b0), "r"(b1));
}

// ---------------------------------------------------------------------------
// fp32 -> (hi, lo) bf16 split, elementwise
// ---------------------------------------------------------------------------
__global__ __launch_bounds__(256)
void split_kernel(const float* __restrict__ in, __nv_bfloat16* __restrict__ hi,
                  __nv_bfloat16* __restrict__ lo, int n4)
{
    int i = blockIdx.x * 256 + threadIdx.x;
    if (i >= n4) return;
    float4 v = reinterpret_cast<const float4*>(in)[i];
    float a[4] = {v.x, v.y, v.z, v.w};
    union { __nv_bfloat16 h[4]; uint2 u; } H, L;
#pragma unroll
    for (int j = 0; j < 4; j++) {
        H.h[j] = __float2bfloat16(a[j]);
        L.h[j] = __float2bfloat16(a[j] - __bfloat162float(H.h[j]));
    }
    reinterpret_cast<uint2*>(hi)[i] = H.u;
    reinterpret_cast<uint2*>(lo)[i] = L.u;
}

// ---------------------------------------------------------------------------
// Transpose V slice of qkv: vt[b][c][s] = qkv[b*SEQ + s][2*DM + c]
// ---------------------------------------------------------------------------
__global__ __launch_bounds__(256)
void transpose_v_kernel(const __nv_bfloat16* __restrict__ qhi,
                        const __nv_bfloat16* __restrict__ qlo,
                        __nv_bfloat16* __restrict__ vthi,
                        __nv_bfloat16* __restrict__ vtlo)
{
    __shared__ __nv_bfloat16 t[32][33];
    const int b   = blockIdx.z >> 1;
    const int sel = blockIdx.z & 1;
    const __nv_bfloat16* src = sel ? qlo : qhi;
    __nv_bfloat16* dst = sel ? vtlo : vthi;

    const int s0 = blockIdx.x * 32;
    const int c0 = blockIdx.y * 32;
    const int tx = threadIdx.x & 31;
    const int ty = threadIdx.x >> 5;
#pragma unroll
    for (int j = 0; j < 4; j++) {
        int s = s0 + ty + 8 * j;
        t[ty + 8 * j][tx] = src[((size_t)b * SEQ + s) * DM3 + 2 * DM + c0 + tx];
    }
    __syncthreads();
#pragma unroll
    for (int j = 0; j < 4; j++) {
        int c = c0 + ty + 8 * j;
        dst[(size_t)b * DM * SEQ + (size_t)c * SEQ + s0 + tx] = t[tx][ty + 8 * j];
    }
}

// ---------------------------------------------------------------------------
// Length-aware causal softmax: row b*SEQ+t. Reads only cols <= t; writes
// split-bf16 probs for cols <= t and zeros for t < col < tile_end (the region
// the causally-truncated PV GEMM will read). Nothing else is touched.
// ---------------------------------------------------------------------------
__global__ __launch_bounds__(256)
void softmax_split_kernel(const float* __restrict__ S,
                          __nv_bfloat16* __restrict__ phi,
                          __nv_bfloat16* __restrict__ plo)
{
    const size_t row = blockIdx.x;
    const int t = (int)(row & (SEQ - 1));
    const int tile_end = ((t >> 7) + 1) << 7;
    const float* p = S + row * (size_t)SEQ;
    const int tid = threadIdx.x;

    float v[16];
#pragma unroll
    for (int i = 0; i < 16; i++) {
        int idx = tid + (i << 8);
        v[i] = (idx <= t) ? p[idx] : -INFINITY;
    }

    float m = -INFINITY;
#pragma unroll
    for (int i = 0; i < 16; i++) m = fmaxf(m, v[i]);
#pragma unroll
    for (int o = 16; o > 0; o >>= 1)
        m = fmaxf(m, __shfl_xor_sync(0xffffffffu, m, o));

    __shared__ float redm[8], reds[8];
    if ((tid & 31) == 0) redm[tid >> 5] = m;
    __syncthreads();
    m = fmaxf(fmaxf(fmaxf(redm[0], redm[1]), fmaxf(redm[2], redm[3])),
              fmaxf(fmaxf(redm[4], redm[5]), fmaxf(redm[6], redm[7])));

    float s = 0.0f;
#pragma unroll
    for (int i = 0; i < 16; i++) {
        v[i] = expf(v[i] - m);   // exp(-inf - m) == 0
        s += v[i];
    }
#pragma unroll
    for (int o = 16; o > 0; o >>= 1)
        s += __shfl_xor_sync(0xffffffffu, s, o);
    if ((tid & 31) == 0) reds[tid >> 5] = s;
    __syncthreads();
    s = reds[0] + reds[1] + reds[2] + reds[3] +
        reds[4] + reds[5] + reds[6] + reds[7];

    const float inv = 1.0f / s;
#pragma unroll
    for (int i = 0; i < 16; i++) {
        int idx = tid + (i << 8);
        if (idx >= tile_end) continue;
        size_t o = row * (size_t)SEQ + idx;
        if (idx <= t) {
            float w = v[i] * inv;
            __nv_bfloat16 h = __float2bfloat16(w);
            __nv_bfloat16 l = __float2bfloat16(w - __bfloat162float(h));
            phi[o] = h; plo[o] = l;
        } else {
            phi[o] = __float2bfloat16(0.0f);
            plo[o] = __float2bfloat16(0.0f);
        }
    }
}

// ---------------------------------------------------------------------------
// Warp-MMA split-bf16 GEMM: C[M,N] = A[M,K] * B[N,K]^T (fp32-accurate via
// 3-term Markidis: AhiBhi + AloBhi + AhiBlo, fp32 accumulate in HMMA).
// CTA tile 128x128, 8 warps -> warp tile 32x64 (2 m16 x 8 n8 frags).
// K chunk 32, cp.async double buffer, padded smem stride 40 elems.
// OUT_SPLIT: 0 -> fp32*scale out, 1 -> split-bf16 out
// CAUSAL_SKIP: skip tiles fully above diagonal (no writes at all)
// KTRUNC: truncate K at m0+128 (PV)
// ---------------------------------------------------------------------------
#define GBM 128
#define GBN 128
#define GKC 32
#define SKP 40                       // padded row stride, elems
#define TILE_BYTES (128 * SKP * 2)   // 10240
#define A_HI_OFF 0
#define A_LO_OFF (TILE_BYTES)
#define B_HI_OFF (2 * TILE_BYTES)
#define B_LO_OFF (3 * TILE_BYTES)
#define BUF_BYTES (4 * TILE_BYTES)   // 40960
#define GSMEM (2 * BUF_BYTES)        // 81920

__device__ __forceinline__ void cp_tile(uint32_t sbase,
        const __nv_bfloat16* __restrict__ g, int ld, int row0, int k0, int tid)
{
#pragma unroll
    for (int it = 0; it < 2; ++it) {
        int v = it * 256 + tid;
        int r = v >> 2;
        int c8 = (v & 3) << 3;                       // 8 bf16 = 16B
        uint32_t dst = sbase + (uint32_t)(r * (SKP * 2) + c8 * 2);
        const void* src = g + (size_t)(row0 + r) * ld + k0 + c8;
        CP_ASYNC16(dst, src);
    }
}

template <int OUT_SPLIT, int CAUSAL_SKIP, int KTRUNC>
__global__ __launch_bounds__(256)
void gemm_mma_kernel(const __nv_bfloat16* __restrict__ Ahi_,
                     const __nv_bfloat16* __restrict__ Alo_, int lda,
                     const __nv_bfloat16* __restrict__ Bhi_,
                     const __nv_bfloat16* __restrict__ Blo_, int ldb,
                     int K,
                     float* __restrict__ outF_,
                     __nv_bfloat16* __restrict__ outHi_,
                     __nv_bfloat16* __restrict__ outLo_, int ldc,
                     size_t sA, size_t sB, size_t sC, float scale)
{
    const int m0 = blockIdx.y * GBM;
    const int n0 = blockIdx.x * GBN;
    if (CAUSAL_SKIP && n0 > m0) return;   // fully above diagonal: nothing

    extern __shared__ char smem[];
    const uint32_t sb = smem_to_u32(smem);
    const int tid = threadIdx.x;
    const int w   = tid >> 5;
    const int lane = tid & 31;
    const int group = lane >> 2;          // 0..7
    const int tig   = lane & 3;           // 0..3
    const int wr = w >> 1;                // 0..3 (M)
    const int wc = w & 1;                 // 0..1 (N)
    const int b  = blockIdx.z;

    const __nv_bfloat16* Ahi = Ahi_ + (size_t)b * sA;
    const __nv_bfloat16* Alo = Alo_ + (size_t)b * sA;
    const __nv_bfloat16* Bhi = Bhi_ + (size_t)b * sB;
    const __nv_bfloat16* Blo = Blo_ + (size_t)b * sB;

    const int K_eff = KTRUNC ? (m0 + GBM) : K;
    const int nc = K_eff / GKC;

    float acc[2][8][4];
#pragma unroll
    for (int t = 0; t < 2; t++)
#pragma unroll
        for (int n = 0; n < 8; n++)
#pragma unroll
            for (int j = 0; j < 4; j++) acc[t][n][j] = 0.0f;

    // prologue: chunk 0
    {
        uint32_t buf = sb;
        cp_tile(buf + A_HI_OFF, Ahi, lda, m0, 0, tid);
        cp_tile(buf + A_LO_OFF, Alo, lda, m0, 0, tid);
        cp_tile(buf + B_HI_OFF, Bhi, ldb, n0, 0, tid);
        cp_tile(buf + B_LO_OFF, Blo, ldb, n0, 0, tid);
        CP_COMMIT();
    }

    for (int c = 0; c < nc; ++c) {
        if (c + 1 < nc) {
            uint32_t buf = sb + ((c + 1) & 1) * BUF_BYTES;
            const int k0 = (c + 1) * GKC;
            cp_tile(buf + A_HI_OFF, Ahi, lda, m0, k0, tid);
            cp_tile(buf + A_LO_OFF, Alo, lda, m0, k0, tid);
            cp_tile(buf + B_HI_OFF, Bhi, ldb, n0, k0, tid);
            cp_tile(buf + B_LO_OFF, Blo, ldb, n0, k0, tid);
            CP_COMMIT();
            CP_WAIT(1);
        } else {
            CP_WAIT(0);
        }
        __syncthreads();

        const uint32_t buf = sb + (c & 1) * BUF_BYTES;
#pragma unroll
        for (int kk = 0; kk < GKC; kk += 16) {
            uint32_t ah[2][4], ax[2][4], bb[8][2];
            // A-hi fragments
#pragma unroll
            for (int t = 0; t < 2; t++) {
                const int r = wr * 32 + t * 16 + group;
                const uint32_t base = buf + A_HI_OFF;
                ah[t][0] = lds_u32(base + (uint32_t)((r)     * SKP + kk + tig * 2) * 2);
                ah[t][1] = lds_u32(base + (uint32_t)((r + 8) * SKP + kk + tig * 2) * 2);
                ah[t][2] = lds_u32(base + (uint32_t)((r)     * SKP + kk + 8 + tig * 2) * 2);
                ah[t][3] = lds_u32(base + (uint32_t)((r + 8) * SKP + kk + 8 + tig * 2) * 2);
            }
            // B-hi fragments
#pragma unroll
            for (int n = 0; n < 8; n++) {
                const int nr = wc * 64 + n * 8 + group;
                const uint32_t base = buf + B_HI_OFF;
                bb[n][0] = lds_u32(base + (uint32_t)(nr * SKP + kk + tig * 2) * 2);
                bb[n][1] = lds_u32(base + (uint32_t)(nr * SKP + kk + 8 + tig * 2) * 2);
            }
            // pass 1: Ahi * Bhi
#pragma unroll
            for (int t = 0; t < 2; t++)
#pragma unroll
                for (int n = 0; n < 8; n++)
                    mma16816(acc[t][n], ah[t][0], ah[t][1], ah[t][2], ah[t][3],
                             bb[n][0], bb[n][1]);
            // pass 2: Alo * Bhi
#pragma unroll
            for (int t = 0; t < 2; t++) {
                const int r = wr * 32 + t * 16 + group;
                const uint32_t base = buf + A_LO_OFF;
                ax[t][0] = lds_u32(base + (uint32_t)((r)     * SKP + kk + tig * 2) * 2);
                ax[t][1] = lds_u32(base + (uint32_t)((r + 8) * SKP + kk + tig * 2) * 2);
                ax[t][2] = lds_u32(base + (uint32_t)((r)     * SKP + kk + 8 + tig * 2) * 2);
                ax[t][3] = lds_u32(base + (uint32_t)((r + 8) * SKP + kk + 8 + tig * 2) * 2);
            }
#pragma unroll
            for (int t = 0; t < 2; t++)
#pragma unroll
                for (int n = 0; n < 8; n++)
                    mma16816(acc[t][n], ax[t][0], ax[t][1], ax[t][2], ax[t][3],
                             bb[n][0], bb[n][1]);
            // pass 3: Ahi * Blo  (reuse bb regs)
#pragma unroll
            for (int n = 0; n < 8; n++) {
                const int nr = wc * 64 + n * 8 + group;
                const uint32_t base = buf + B_LO_OFF;
                bb[n][0] = lds_u32(base + (uint32_t)(nr * SKP + kk + tig * 2) * 2);
                bb[n][1] = lds_u32(base + (uint32_t)(nr * SKP + kk + 8 + tig * 2) * 2);
            }
#pragma unroll
            for (int t = 0; t < 2; t++)
#pragma unroll
                for (int n = 0; n < 8; n++)
                    mma16816(acc[t][n], ah[t][0], ah[t][1], ah[t][2], ah[t][3],
                             bb[n][0], bb[n][1]);
        }
        __syncthreads();
    }

    // Epilogue
#pragma unroll
    for (int t = 0; t < 2; t++) {
        const int row = m0 + wr * 32 + t * 16 + group;
#pragma unroll
        for (int n = 0; n < 8; n++) {
            const int col = n0 + wc * 64 + n * 8 + tig * 2;
            if (OUT_SPLIT == 0) {
                float* dst = outF_ + (size_t)b * sC;
                float2 v0 = make_float2(acc[t][n][0] * scale, acc[t][n][1] * scale);
                float2 v1 = make_float2(acc[t][n][2] * scale, acc[t][n][3] * scale);
                *reinterpret_cast<float2*>(dst + (size_t)row * ldc + col) = v0;
                *reinterpret_cast<float2*>(dst + (size_t)(row + 8) * ldc + col) = v1;
            } else {
                __nv_bfloat16* dh = outHi_ + (size_t)b * sC;
                __nv_bfloat16* dl = outLo_ + (size_t)b * sC;
#pragma unroll
                for (int hh = 0; hh < 2; hh++) {
                    const int r = row + hh * 8;
                    float v0 = acc[t][n][hh * 2 + 0];
                    float v1 = acc[t][n][hh * 2 + 1];
                    __nv_bfloat16 h0 = __float2bfloat16(v0);
                    __nv_bfloat16 h1 = __float2bfloat16(v1);
                    __nv_bfloat16 l0 = __float2bfloat16(v0 - __bfloat162float(h0));
                    __nv_bfloat16 l1 = __float2bfloat16(v1 - __bfloat162float(h1));
                    union { __nv_bfloat16 x[2]; uint32_t u; } H, L;
                    H.x[0] = h0; H.x[1] = h1; L.x[0] = l0; L.x[1] = l1;
                    *reinterpret_cast<uint32_t*>(dh + (size_t)r * ldc + col) = H.u;
                    *reinterpret_cast<uint32_t*>(dl + (size_t)r * ldc + col) = L.u;
                }
            }
        }
    }
}

// ---------------------------------------------------------------------------
extern "C" void kernel_launch(void* const* d_in, const int* in_sizes, int n_in,
                              void* d_out, int out_size)
{
    const float* x      = (const float*)d_in[0];   // [B,T,C]
    const float* w_qkv  = (const float*)d_in[1];   // [3C,C]
    const float* w_proj = (const float*)d_in[2];   // [C,C]
    float* out = (float*)d_out;                    // [B,T,C]

    __nv_bfloat16 *xhi, *xlo, *wqhi, *wqlo, *wphi, *wplo;
    __nv_bfloat16 *qkvhi, *qkvlo, *phi, *plo, *vthi, *vtlo, *atthi, *attlo;
    float* scores;
    cudaGetSymbolAddress((void**)&xhi, g_xhi);     cudaGetSymbolAddress((void**)&xlo, g_xlo);
    cudaGetSymbolAddress((void**)&wqhi, g_wqhi);   cudaGetSymbolAddress((void**)&wqlo, g_wqlo);
    cudaGetSymbolAddress((void**)&wphi, g_wphi);   cudaGetSymbolAddress((void**)&wplo, g_wplo);
    cudaGetSymbolAddress((void**)&qkvhi, g_qkvhi); cudaGetSymbolAddress((void**)&qkvlo, g_qkvlo);
    cudaGetSymbolAddress((void**)&scores, g_scores);
    cudaGetSymbolAddress((void**)&phi, g_phi);     cudaGetSymbolAddress((void**)&plo, g_plo);
    cudaGetSymbolAddress((void**)&vthi, g_vthi);   cudaGetSymbolAddress((void**)&vtlo, g_vtlo);
    cudaGetSymbolAddress((void**)&atthi, g_atthi); cudaGetSymbolAddress((void**)&attlo, g_attlo);

    cudaFuncSetAttribute(gemm_mma_kernel<0,0,0>, cudaFuncAttributeMaxDynamicSharedMemorySize, GSMEM);
    cudaFuncSetAttribute(gemm_mma_kernel<1,0,0>, cudaFuncAttributeMaxDynamicSharedMemorySize, GSMEM);
    cudaFuncSetAttribute(gemm_mma_kernel<0,1,0>, cudaFuncAttributeMaxDynamicSharedMemorySize, GSMEM);
    cudaFuncSetAttribute(gemm_mma_kernel<1,0,1>, cudaFuncAttributeMaxDynamicSharedMemorySize, GSMEM);

    const float scale = 1.0f / sqrtf((float)DM);

    // 0) split fp32 inputs into (hi, lo) bf16
    {
        int n4 = (int)(NX / 4);
        split_kernel<<<(n4 + 255) / 256, 256>>>(x, xhi, xlo, n4);
        int w4 = DM3 * DM / 4;
        split_kernel<<<(w4 + 255) / 256, 256>>>(w_qkv, wqhi, wqlo, w4);
        int p4 = DM * DM / 4;
        split_kernel<<<(p4 + 255) / 256, 256>>>(w_proj, wphi, wplo, p4);
    }

    // 1) qkv = x @ w_qkv^T -> split-bf16    [16384 x 1536 x 512]
    gemm_mma_kernel<1,0,0><<<dim3(DM3 / GBN, (BATCH * SEQ) / GBM, 1), 256, GSMEM>>>(
        xhi, xlo, DM, wqhi, wqlo, DM, DM,
        nullptr, qkvhi, qkvlo, DM3, 0, 0, 0, 1.0f);

    // 2) transpose V: vt[b][c][s]
    transpose_v_kernel<<<dim3(SEQ / 32, DM / 32, BATCH * 2), 256>>>(
        qkvhi, qkvlo, vthi, vtlo);

    // 3) scores = (Q @ K^T) * scale -> fp32, lower-triangle tiles only
    gemm_mma_kernel<0,1,0><<<dim3(SEQ / GBN, SEQ / GBM, BATCH), 256, GSMEM>>>(
        qkvhi, qkvlo, DM3, qkvhi + DM, qkvlo + DM, DM3, DM,
        scores, nullptr, nullptr, SEQ,
        (size_t)SEQ * DM3, (size_t)SEQ * DM3, (size_t)SEQ * SEQ, scale);

    // 4) causal softmax -> split-bf16 P (zeros up to row-tile boundary)
    softmax_split_kernel<<<BATCH * SEQ, 256>>>(scores, phi, plo);

    // 5) att = P @ V (K truncated causally) -> split-bf16
    gemm_mma_kernel<1,0,1><<<dim3(DM / GBN, SEQ / GBM, BATCH), 256, GSMEM>>>(
        phi, plo, SEQ, vthi, vtlo, SEQ, SEQ,
        nullptr, atthi, attlo, DM,
        (size_t)SEQ * SEQ, (size_t)DM * SEQ, (size_t)SEQ * DM, 1.0f);

    // 6) out = att @ w_proj^T -> fp32
    gemm_mma_kernel<0,0,0><<<dim3(DM / GBN, (BATCH * SEQ) / GBM, 1), 256, GSMEM>>>(
        atthi, attlo, DM, wphi, wplo, DM, DM,
        out, nullptr, nullptr, DM, 0, 0, 0, 1.0f);
}

// round 8
// speedup vs baseline: 2.5393x; 1.1188x over previous
#include <cuda_runtime.h>
#include <cuda_bf16.h>
#include <cstdint>
#include <math.h>

// Problem constants (B=4, T=4096, C=512)
#define BATCH 4
#define SEQ   4096
#define DM    512
#define DM3   1536

// ---------------------------------------------------------------------------
// Scratch (device globals; no allocation allowed)
// ---------------------------------------------------------------------------
#define NX   ((size_t)BATCH * SEQ * DM)
#define NQKV ((size_t)BATCH * SEQ * DM3)
#define NS   ((size_t)BATCH * SEQ * SEQ)

__device__ __nv_bfloat16 g_xhi[NX],   g_xlo[NX];
__device__ __nv_bfloat16 g_wqhi[(size_t)DM3 * DM], g_wqlo[(size_t)DM3 * DM];
__device__ __nv_bfloat16 g_wphi[(size_t)DM * DM],  g_wplo[(size_t)DM * DM];
__device__ __nv_bfloat16 g_qkvhi[NQKV], g_qkvlo[NQKV];
__device__ float         g_scores[NS];
__device__ __nv_bfloat16 g_phi[NS], g_plo[NS];
__device__ __nv_bfloat16 g_vthi[NX], g_vtlo[NX];
__device__ __nv_bfloat16 g_atthi[NX], g_attlo[NX];

// ---------------------------------------------------------------------------
// PTX helpers
// ---------------------------------------------------------------------------
__device__ __forceinline__ uint32_t smem_to_u32(const void* p) {
    uint32_t a;
    asm("{ .reg .u64 t; cvta.to.shared.u64 t, %1; cvt.u32.u64 %0, t; }"
        : "=r"(a) : "l"(p));
    return a;
}
#define CP_ASYNC16(dst, src) \
    asm volatile("cp.async.ca.shared.global [%0], [%1], 16;" :: "r"(dst), "l"(src))
#define CP_COMMIT() asm volatile("cp.async.commit_group;" ::: "memory")
#define CP_WAIT(n)  asm volatile("cp.async.wait_group %0;" :: "n"(n) : "memory")

#define LDSM_X4(r0, r1, r2, r3, addr) \
    asm volatile("ldmatrix.sync.aligned.m8n8.x4.shared.b16 {%0,%1,%2,%3}, [%4];" \
        : "=r"(r0), "=r"(r1), "=r"(r2), "=r"(r3) : "r"(addr))

__device__ __forceinline__ void mma16816(float* c,
        uint32_t a0, uint32_t a1, uint32_t a2, uint32_t a3,
        uint32_t b0, uint32_t b1) {
    asm volatile(
        "mma.sync.aligned.m16n8k16.row.col.f32.bf16.bf16.f32 "
        "{%0,%1,%2,%3}, {%4,%5,%6,%7}, {%8,%9}, {%0,%1,%2,%3};"
        : "+f"(c[0]), "+f"(c[1]), "+f"(c[2]), "+f"(c[3])
        : "r"(a0), "r"(a1), "r"(a2), "r"(a3), "r"(b0), "r"(b1));
}

// ---------------------------------------------------------------------------
// fp32 -> (hi, lo) bf16 split, elementwise
// ---------------------------------------------------------------------------
__global__ __launch_bounds__(256)
void split_kernel(const float* __restrict__ in, __nv_bfloat16* __restrict__ hi,
                  __nv_bfloat16* __restrict__ lo, int n4)
{
    int i = blockIdx.x * 256 + threadIdx.x;
    if (i >= n4) return;
    float4 v = reinterpret_cast<const float4*>(in)[i];
    float a[4] = {v.x, v.y, v.z, v.w};
    union { __nv_bfloat16 h[4]; uint2 u; } H, L;
#pragma unroll
    for (int j = 0; j < 4; j++) {
        H.h[j] = __float2bfloat16(a[j]);
        L.h[j] = __float2bfloat16(a[j] - __bfloat162float(H.h[j]));
    }
    reinterpret_cast<uint2*>(hi)[i] = H.u;
    reinterpret_cast<uint2*>(lo)[i] = L.u;
}

// ---------------------------------------------------------------------------
// Transpose V slice of qkv: vt[b][c][s] = qkv[b*SEQ + s][2*DM + c]
// ---------------------------------------------------------------------------
__global__ __launch_bounds__(256)
void transpose_v_kernel(const __nv_bfloat16* __restrict__ qhi,
                        const __nv_bfloat16* __restrict__ qlo,
                        __nv_bfloat16* __restrict__ vthi,
                        __nv_bfloat16* __restrict__ vtlo)
{
    __shared__ __nv_bfloat16 t[32][33];
    const int b   = blockIdx.z >> 1;
    const int sel = blockIdx.z & 1;
    const __nv_bfloat16* src = sel ? qlo : qhi;
    __nv_bfloat16* dst = sel ? vtlo : vthi;

    const int s0 = blockIdx.x * 32;
    const int c0 = blockIdx.y * 32;
    const int tx = threadIdx.x & 31;
    const int ty = threadIdx.x >> 5;
#pragma unroll
    for (int j = 0; j < 4; j++) {
        int s = s0 + ty + 8 * j;
        t[ty + 8 * j][tx] = src[((size_t)b * SEQ + s) * DM3 + 2 * DM + c0 + tx];
    }
    __syncthreads();
#pragma unroll
    for (int j = 0; j < 4; j++) {
        int c = c0 + ty + 8 * j;
        dst[(size_t)b * DM * SEQ + (size_t)c * SEQ + s0 + tx] = t[tx][ty + 8 * j];
    }
}

// ---------------------------------------------------------------------------
// Length-aware causal softmax -> split-bf16 P (zeros through tile boundary)
// ---------------------------------------------------------------------------
__global__ __launch_bounds__(256)
void softmax_split_kernel(const float* __restrict__ S,
                          __nv_bfloat16* __restrict__ phi,
                          __nv_bfloat16* __restrict__ plo)
{
    const size_t row = blockIdx.x;
    const int t = (int)(row & (SEQ - 1));
    const int tile_end = ((t >> 7) + 1) << 7;
    const float* p = S + row * (size_t)SEQ;
    const int tid = threadIdx.x;

    float v[16];
#pragma unroll
    for (int i = 0; i < 16; i++) {
        int idx = tid + (i << 8);
        v[i] = (idx <= t) ? p[idx] : -INFINITY;
    }

    float m = -INFINITY;
#pragma unroll
    for (int i = 0; i < 16; i++) m = fmaxf(m, v[i]);
#pragma unroll
    for (int o = 16; o > 0; o >>= 1)
        m = fmaxf(m, __shfl_xor_sync(0xffffffffu, m, o));

    __shared__ float redm[8], reds[8];
    if ((tid & 31) == 0) redm[tid >> 5] = m;
    __syncthreads();
    m = fmaxf(fmaxf(fmaxf(redm[0], redm[1]), fmaxf(redm[2], redm[3])),
              fmaxf(fmaxf(redm[4], redm[5]), fmaxf(redm[6], redm[7])));

    float s = 0.0f;
#pragma unroll
    for (int i = 0; i < 16; i++) { v[i] = expf(v[i] - m); s += v[i]; }
#pragma unroll
    for (int o = 16; o > 0; o >>= 1)
        s += __shfl_xor_sync(0xffffffffu, s, o);
    if ((tid & 31) == 0) reds[tid >> 5] = s;
    __syncthreads();
    s = reds[0] + reds[1] + reds[2] + reds[3] +
        reds[4] + reds[5] + reds[6] + reds[7];

    const float inv = 1.0f / s;
#pragma unroll
    for (int i = 0; i < 16; i++) {
        int idx = tid + (i << 8);
        if (idx >= tile_end) continue;
        size_t o = row * (size_t)SEQ + idx;
        if (idx <= t) {
            float w = v[i] * inv;
            __nv_bfloat16 h = __float2bfloat16(w);
            __nv_bfloat16 l = __float2bfloat16(w - __bfloat162float(h));
            phi[o] = h; plo[o] = l;
        } else {
            phi[o] = __float2bfloat16(0.0f);
            plo[o] = __float2bfloat16(0.0f);
        }
    }
}

// ---------------------------------------------------------------------------
// Warp-MMA split-bf16 GEMM with ldmatrix fragment loads.
// C[M,N] = A[M,K] * B[N,K]^T, 3-term Markidis, fp32 accumulate.
// CTA 128x128, 8 warps (32x64 each), K chunk 32, cp.async double buffer.
// ---------------------------------------------------------------------------
#define GBM 128
#define GBN 128
#define GKC 32
#define SKP 40                       // padded row stride, elems
#define TILE_BYTES (128 * SKP * 2)   // 10240
#define A_HI_OFF 0
#define A_LO_OFF (TILE_BYTES)
#define B_HI_OFF (2 * TILE_BYTES)
#define B_LO_OFF (3 * TILE_BYTES)
#define BUF_BYTES (4 * TILE_BYTES)   // 40960
#define GSMEM (2 * BUF_BYTES)        // 81920

__device__ __forceinline__ void cp_tile(uint32_t sbase,
        const __nv_bfloat16* __restrict__ g, int ld, int row0, int k0, int tid)
{
#pragma unroll
    for (int it = 0; it < 2; ++it) {
        int v = it * 256 + tid;
        int r = v >> 2;
        int c8 = (v & 3) << 3;
        uint32_t dst = sbase + (uint32_t)(r * (SKP * 2) + c8 * 2);
        const void* src = g + (size_t)(row0 + r) * ld + k0 + c8;
        CP_ASYNC16(dst, src);
    }
}

template <int OUT_SPLIT, int CAUSAL_SKIP, int KTRUNC>
__global__ __launch_bounds__(256, 2)
void gemm_mma_kernel(const __nv_bfloat16* __restrict__ Ahi_,
                     const __nv_bfloat16* __restrict__ Alo_, int lda,
                     const __nv_bfloat16* __restrict__ Bhi_,
                     const __nv_bfloat16* __restrict__ Blo_, int ldb,
                     int K,
                     float* __restrict__ outF_,
                     __nv_bfloat16* __restrict__ outHi_,
                     __nv_bfloat16* __restrict__ outLo_, int ldc,
                     size_t sA, size_t sB, size_t sC, float scale)
{
    const int m0 = blockIdx.y * GBM;
    const int n0 = blockIdx.x * GBN;
    if (CAUSAL_SKIP && n0 > m0) return;

    extern __shared__ char smem[];
    const uint32_t sb = smem_to_u32(smem);
    const int tid = threadIdx.x;
    const int w    = tid >> 5;
    const int lane = tid & 31;
    const int group = lane >> 2;
    const int tig   = lane & 3;
    const int wr = w >> 1;                // 0..3 (M)
    const int wc = w & 1;                 // 0..1 (N)
    const int b  = blockIdx.z;

    const __nv_bfloat16* Ahi = Ahi_ + (size_t)b * sA;
    const __nv_bfloat16* Alo = Alo_ + (size_t)b * sA;
    const __nv_bfloat16* Bhi = Bhi_ + (size_t)b * sB;
    const __nv_bfloat16* Blo = Blo_ + (size_t)b * sB;

    const int K_eff = KTRUNC ? (m0 + GBM) : K;
    const int nc = K_eff / GKC;

    // ldmatrix per-lane address components
    const int lq = lane >> 3;             // quad 0..3
    const int lw = lane & 7;
    // A: m0=rows+0 k0 | m1=rows+8 k0 | m2=rows+0 k8 | m3=rows+8 k8
    const int a_r = lw + ((lq & 1) << 3);
    const int a_c = (lq & 2) << 2;        // 0 or 8
    // B pair (n, n+1): m0=n rows k0 | m1=n rows k8 | m2=n+1 rows k0 | m3=n+1 k8
    const int b_r = lw + ((lq >> 1) << 3);
    const int b_c = (lq & 1) << 3;
    // byte offsets within a tile (before kk)
    const uint32_t aoff0 = (uint32_t)((wr * 32 + a_r) * SKP + a_c) * 2;       // t=0
    const uint32_t aoff1 = (uint32_t)((wr * 32 + 16 + a_r) * SKP + a_c) * 2;  // t=1
    uint32_t boff[4];
#pragma unroll
    for (int ng = 0; ng < 4; ng++)
        boff[ng] = (uint32_t)((wc * 64 + ng * 16 + b_r) * SKP + b_c) * 2;

    float acc[2][8][4];
#pragma unroll
    for (int t = 0; t < 2; t++)
#pragma unroll
        for (int n = 0; n < 8; n++)
#pragma unroll
            for (int j = 0; j < 4; j++) acc[t][n][j] = 0.0f;

    // prologue: chunk 0
    {
        cp_tile(sb + A_HI_OFF, Ahi, lda, m0, 0, tid);
        cp_tile(sb + A_LO_OFF, Alo, lda, m0, 0, tid);
        cp_tile(sb + B_HI_OFF, Bhi, ldb, n0, 0, tid);
        cp_tile(sb + B_LO_OFF, Blo, ldb, n0, 0, tid);
        CP_COMMIT();
    }

    for (int c = 0; c < nc; ++c) {
        if (c + 1 < nc) {
            uint32_t buf = sb + ((c + 1) & 1) * BUF_BYTES;
            const int k0 = (c + 1) * GKC;
            cp_tile(buf + A_HI_OFF, Ahi, lda, m0, k0, tid);
            cp_tile(buf + A_LO_OFF, Alo, lda, m0, k0, tid);
            cp_tile(buf + B_HI_OFF, Bhi, ldb, n0, k0, tid);
            cp_tile(buf + B_LO_OFF, Blo, ldb, n0, k0, tid);
            CP_COMMIT();
            CP_WAIT(1);
        } else {
            CP_WAIT(0);
        }
        __syncthreads();

        const uint32_t buf = sb + (c & 1) * BUF_BYTES;
#pragma unroll
        for (int kk = 0; kk < GKC; kk += 16) {
            const uint32_t kb = (uint32_t)kk * 2;
            uint32_t ah[2][4], ax[2][4], bb[8][2];

            LDSM_X4(ah[0][0], ah[0][1], ah[0][2], ah[0][3], buf + A_HI_OFF + aoff0 + kb);
            LDSM_X4(ah[1][0], ah[1][1], ah[1][2], ah[1][3], buf + A_HI_OFF + aoff1 + kb);
#pragma unroll
            for (int ng = 0; ng < 4; ng++)
                LDSM_X4(bb[2 * ng][0], bb[2 * ng][1], bb[2 * ng + 1][0], bb[2 * ng + 1][1],
                        buf + B_HI_OFF + boff[ng] + kb);
            // pass 1: Ahi * Bhi
#pragma unroll
            for (int t = 0; t < 2; t++)
#pragma unroll
                for (int n = 0; n < 8; n++)
                    mma16816(acc[t][n], ah[t][0], ah[t][1], ah[t][2], ah[t][3],
                             bb[n][0], bb[n][1]);
            // pass 2: Alo * Bhi
            LDSM_X4(ax[0][0], ax[0][1], ax[0][2], ax[0][3], buf + A_LO_OFF + aoff0 + kb);
            LDSM_X4(ax[1][0], ax[1][1], ax[1][2], ax[1][3], buf + A_LO_OFF + aoff1 + kb);
#pragma unroll
            for (int t = 0; t < 2; t++)
#pragma unroll
                for (int n = 0; n < 8; n++)
                    mma16816(acc[t][n], ax[t][0], ax[t][1], ax[t][2], ax[t][3],
                             bb[n][0], bb[n][1]);
            // pass 3: Ahi * Blo
#pragma unroll
            for (int ng = 0; ng < 4; ng++)
                LDSM_X4(bb[2 * ng][0], bb[2 * ng][1], bb[2 * ng + 1][0], bb[2 * ng + 1][1],
                        buf + B_LO_OFF + boff[ng] + kb);
#pragma unroll
            for (int t = 0; t < 2; t++)
#pragma unroll
                for (int n = 0; n < 8; n++)
                    mma16816(acc[t][n], ah[t][0], ah[t][1], ah[t][2], ah[t][3],
                             bb[n][0], bb[n][1]);
        }
        __syncthreads();
    }

    // Epilogue
#pragma unroll
    for (int t = 0; t < 2; t++) {
        const int row = m0 + wr * 32 + t * 16 + group;
#pragma unroll
        for (int n = 0; n < 8; n++) {
            const int col = n0 + wc * 64 + n * 8 + tig * 2;
            if (OUT_SPLIT == 0) {
                float* dst = outF_ + (size_t)b * sC;
                float2 v0 = make_float2(acc[t][n][0] * scale, acc[t][n][1] * scale);
                float2 v1 = make_float2(acc[t][n][2] * scale, acc[t][n][3] * scale);
                *reinterpret_cast<float2*>(dst + (size_t)row * ldc + col) = v0;
                *reinterpret_cast<float2*>(dst + (size_t)(row + 8) * ldc + col) = v1;
            } else {
                __nv_bfloat16* dh = outHi_ + (size_t)b * sC;
                __nv_bfloat16* dl = outLo_ + (size_t)b * sC;
#pragma unroll
                for (int hh = 0; hh < 2; hh++) {
                    const int r = row + hh * 8;
                    float v0 = acc[t][n][hh * 2 + 0];
                    float v1 = acc[t][n][hh * 2 + 1];
                    __nv_bfloat16 h0 = __float2bfloat16(v0);
                    __nv_bfloat16 h1 = __float2bfloat16(v1);
                    __nv_bfloat16 l0 = __float2bfloat16(v0 - __bfloat162float(h0));
                    __nv_bfloat16 l1 = __float2bfloat16(v1 - __bfloat162float(h1));
                    union { __nv_bfloat16 x[2]; uint32_t u; } H, L;
                    H.x[0] = h0; H.x[1] = h1; L.x[0] = l0; L.x[1] = l1;
                    *reinterpret_cast<uint32_t*>(dh + (size_t)r * ldc + col) = H.u;
                    *reinterpret_cast<uint32_t*>(dl + (size_t)r * ldc + col) = L.u;
                }
            }
        }
    }
}

// ---------------------------------------------------------------------------
extern "C" void kernel_launch(void* const* d_in, const int* in_sizes, int n_in,
                              void* d_out, int out_size)
{
    const float* x      = (const float*)d_in[0];   // [B,T,C]
    const float* w_qkv  = (const float*)d_in[1];   // [3C,C]
    const float* w_proj = (const float*)d_in[2];   // [C,C]
    float* out = (float*)d_out;                    // [B,T,C]

    __nv_bfloat16 *xhi, *xlo, *wqhi, *wqlo, *wphi, *wplo;
    __nv_bfloat16 *qkvhi, *qkvlo, *phi, *plo, *vthi, *vtlo, *atthi, *attlo;
    float* scores;
    cudaGetSymbolAddress((void**)&xhi, g_xhi);     cudaGetSymbolAddress((void**)&xlo, g_xlo);
    cudaGetSymbolAddress((void**)&wqhi, g_wqhi);   cudaGetSymbolAddress((void**)&wqlo, g_wqlo);
    cudaGetSymbolAddress((void**)&wphi, g_wphi);   cudaGetSymbolAddress((void**)&wplo, g_wplo);
    cudaGetSymbolAddress((void**)&qkvhi, g_qkvhi); cudaGetSymbolAddress((void**)&qkvlo, g_qkvlo);
    cudaGetSymbolAddress((void**)&scores, g_scores);
    cudaGetSymbolAddress((void**)&phi, g_phi);     cudaGetSymbolAddress((void**)&plo, g_plo);
    cudaGetSymbolAddress((void**)&vthi, g_vthi);   cudaGetSymbolAddress((void**)&vtlo, g_vtlo);
    cudaGetSymbolAddress((void**)&atthi, g_atthi); cudaGetSymbolAddress((void**)&attlo, g_attlo);

    cudaFuncSetAttribute(gemm_mma_kernel<0,0,0>, cudaFuncAttributeMaxDynamicSharedMemorySize, GSMEM);
    cudaFuncSetAttribute(gemm_mma_kernel<1,0,0>, cudaFuncAttributeMaxDynamicSharedMemorySize, GSMEM);
    cudaFuncSetAttribute(gemm_mma_kernel<0,1,0>, cudaFuncAttributeMaxDynamicSharedMemorySize, GSMEM);
    cudaFuncSetAttribute(gemm_mma_kernel<1,0,1>, cudaFuncAttributeMaxDynamicSharedMemorySize, GSMEM);

    const float scale = 1.0f / sqrtf((float)DM);

    // 0) split fp32 inputs into (hi, lo) bf16
    {
        int n4 = (int)(NX / 4);
        split_kernel<<<(n4 + 255) / 256, 256>>>(x, xhi, xlo, n4);
        int w4 = DM3 * DM / 4;
        split_kernel<<<(w4 + 255) / 256, 256>>>(w_qkv, wqhi, wqlo, w4);
        int p4 = DM * DM / 4;
        split_kernel<<<(p4 + 255) / 256, 256>>>(w_proj, wphi, wplo, p4);
    }

    // 1) qkv = x @ w_qkv^T -> split-bf16
    gemm_mma_kernel<1,0,0><<<dim3(DM3 / GBN, (BATCH * SEQ) / GBM, 1), 256, GSMEM>>>(
        xhi, xlo, DM, wqhi, wqlo, DM, DM,
        nullptr, qkvhi, qkvlo, DM3, 0, 0, 0, 1.0f);

    // 2) transpose V: vt[b][c][s]
    transpose_v_kernel<<<dim3(SEQ / 32, DM / 32, BATCH * 2), 256>>>(
        qkvhi, qkvlo, vthi, vtlo);

    // 3) scores = (Q @ K^T) * scale -> fp32, lower-triangle tiles only
    gemm_mma_kernel<0,1,0><<<dim3(SEQ / GBN, SEQ / GBM, BATCH), 256, GSMEM>>>(
        qkvhi, qkvlo, DM3, qkvhi + DM, qkvlo + DM, DM3, DM,
        scores, nullptr, nullptr, SEQ,
        (size_t)SEQ * DM3, (size_t)SEQ * DM3, (size_t)SEQ * SEQ, scale);

    // 4) causal softmax -> split-bf16 P
    softmax_split_kernel<<<BATCH * SEQ, 256>>>(scores, phi, plo);

    // 5) att = P @ V (K truncated causally) -> split-bf16
    gemm_mma_kernel<1,0,1><<<dim3(DM / GBN, SEQ / GBM, BATCH), 256, GSMEM>>>(
        phi, plo, SEQ, vthi, vtlo, SEQ, SEQ,
        nullptr, atthi, attlo, DM,
        (size_t)SEQ * SEQ, (size_t)DM * SEQ, (size_t)SEQ * DM, 1.0f);

    // 6) out = att @ w_proj^T -> fp32
    gemm_mma_kernel<0,0,0><<<dim3(DM / GBN, (BATCH * SEQ) / GBM, 1), 256, GSMEM>>>(
        atthi, attlo, DM, wphi, wplo, DM, DM,
        out, nullptr, nullptr, DM, 0, 0, 0, 1.0f);
}

// round 10
// speedup vs baseline: 3.5332x; 1.3914x over previous
#include <cuda_runtime.h>
#include <cuda_fp16.h>
#include <cstdint>
#include <math.h>

// Problem constants (B=4, T=4096, C=512)
#define BATCH 4
#define SEQ   4096
#define DM    512
#define DM3   1536

// ---------------------------------------------------------------------------
// Scratch (device globals; no allocation allowed)
// ---------------------------------------------------------------------------
#define NX   ((size_t)BATCH * SEQ * DM)
#define NQKV ((size_t)BATCH * SEQ * DM3)
#define NS   ((size_t)BATCH * SEQ * SEQ)

__device__ __half g_xhi[NX],   g_xlo[NX];
__device__ __half g_wqhi[(size_t)DM3 * DM];
__device__ __half g_wphi[(size_t)DM * DM];
__device__ __half g_qkvhi[NQKV], g_qkvlo[NQKV];
__device__ float  g_scores[NS];
__device__ __half g_phi[NS], g_plo[NS];
__device__ __half g_vthi[NX];
__device__ __half g_atthi[NX], g_attlo[NX];

// ---------------------------------------------------------------------------
// PTX helpers
// ---------------------------------------------------------------------------
__device__ __forceinline__ uint32_t smem_to_u32(const void* p) {
    uint32_t a;
    asm("{ .reg .u64 t; cvta.to.shared.u64 t, %1; cvt.u32.u64 %0, t; }"
        : "=r"(a) : "l"(p));
    return a;
}
#define CP_ASYNC16(dst, src) \
    asm volatile("cp.async.cg.shared.global [%0], [%1], 16;" :: "r"(dst), "l"(src))
#define CP_COMMIT() asm volatile("cp.async.commit_group;" ::: "memory")
#define CP_WAIT(n)  asm volatile("cp.async.wait_group %0;" :: "n"(n) : "memory")

#define LDSM_X4(r0, r1, r2, r3, addr) \
    asm volatile("ldmatrix.sync.aligned.m8n8.x4.shared.b16 {%0,%1,%2,%3}, [%4];" \
        : "=r"(r0), "=r"(r1), "=r"(r2), "=r"(r3) : "r"(addr))

__device__ __forceinline__ void mma16816(float* c,
        uint32_t a0, uint32_t a1, uint32_t a2, uint32_t a3,
        uint32_t b0, uint32_t b1) {
    asm volatile(
        "mma.sync.aligned.m16n8k16.row.col.f32.f16.f16.f32 "
        "{%0,%1,%2,%3}, {%4,%5,%6,%7}, {%8,%9}, {%0,%1,%2,%3};"
        : "+f"(c[0]), "+f"(c[1]), "+f"(c[2]), "+f"(c[3])
        : "r"(a0), "r"(a1), "r"(a2), "r"(a3), "r"(b0), "r"(b1));
}

__device__ __forceinline__ void split_f32(float v, __half& h, __half& l) {
    h = __float2half_rn(v);
    l = __float2half_rn(v - __half2float(h));
}

// ---------------------------------------------------------------------------
// fp32 -> (hi, lo) fp16 split (lo optional)
// ---------------------------------------------------------------------------
__global__ __launch_bounds__(256)
void split_kernel(const float* __restrict__ in, __half* __restrict__ hi,
                  __half* __restrict__ lo, int n4)
{
    int i = blockIdx.x * 256 + threadIdx.x;
    if (i >= n4) return;
    float4 v = reinterpret_cast<const float4*>(in)[i];
    float a[4] = {v.x, v.y, v.z, v.w};
    union { __half h[4]; uint2 u; } H, L;
#pragma unroll
    for (int j = 0; j < 4; j++) split_f32(a[j], H.h[j], L.h[j]);
    reinterpret_cast<uint2*>(hi)[i] = H.u;
    if (lo) reinterpret_cast<uint2*>(lo)[i] = L.u;
}

// ---------------------------------------------------------------------------
// Transpose V-hi slice of qkv: vt[b][c][s] = qkvhi[b*SEQ + s][2*DM + c]
// ---------------------------------------------------------------------------
__global__ __launch_bounds__(256)
void transpose_v_kernel(const __half* __restrict__ qhi,
                        __half* __restrict__ vthi)
{
    __shared__ __half t[32][33];
    const int b  = blockIdx.z;
    const int s0 = blockIdx.x * 32;
    const int c0 = blockIdx.y * 32;
    const int tx = threadIdx.x & 31;
    const int ty = threadIdx.x >> 5;
#pragma unroll
    for (int j = 0; j < 4; j++) {
        int s = s0 + ty + 8 * j;
        t[ty + 8 * j][tx] = qhi[((size_t)b * SEQ + s) * DM3 + 2 * DM + c0 + tx];
    }
    __syncthreads();
#pragma unroll
    for (int j = 0; j < 4; j++) {
        int c = c0 + ty + 8 * j;
        vthi[(size_t)b * DM * SEQ + (size_t)c * SEQ + s0 + tx] = t[tx][ty + 8 * j];
    }
}

// ---------------------------------------------------------------------------
// Causal softmax over valid prefix only; exp once per element via smem row
// buffer; writes split-fp16 P for cols<=t, zeros to the 128-tile boundary.
// ---------------------------------------------------------------------------
__global__ __launch_bounds__(256)
void softmax_split_kernel(const float* __restrict__ S,
                          __half* __restrict__ phi,
                          __half* __restrict__ plo)
{
    __shared__ float e[SEQ];          // 16 KB row buffer
    __shared__ float redm[8], reds[8];
    const size_t row = blockIdx.x;
    const int t = (int)(row & (SEQ - 1));
    const int nval = t + 1;
    const int tile_end = ((t >> 7) + 1) << 7;
    const float* p = S + row * (size_t)SEQ;
    const int tid = threadIdx.x;

    float m = -INFINITY;
    for (int i = tid; i < nval; i += 256) m = fmaxf(m, p[i]);
#pragma unroll
    for (int o = 16; o > 0; o >>= 1)
        m = fmaxf(m, __shfl_xor_sync(0xffffffffu, m, o));
    if ((tid & 31) == 0) redm[tid >> 5] = m;
    __syncthreads();
    m = fmaxf(fmaxf(fmaxf(redm[0], redm[1]), fmaxf(redm[2], redm[3])),
              fmaxf(fmaxf(redm[4], redm[5]), fmaxf(redm[6], redm[7])));

    float s = 0.0f;
    for (int i = tid; i < nval; i += 256) {
        float ev = __expf(p[i] - m);
        e[i] = ev;
        s += ev;
    }
#pragma unroll
    for (int o = 16; o > 0; o >>= 1)
        s += __shfl_xor_sync(0xffffffffu, s, o);
    if ((tid & 31) == 0) reds[tid >> 5] = s;
    __syncthreads();
    s = reds[0] + reds[1] + reds[2] + reds[3] +
        reds[4] + reds[5] + reds[6] + reds[7];

    const float inv = 1.0f / s;
    for (int i = tid; i < tile_end; i += 256) {
        float w = (i < nval) ? e[i] * inv : 0.0f;
        __half h, l;
        split_f32(w, h, l);
        size_t o = row * (size_t)SEQ + i;
        phi[o] = h; plo[o] = l;
    }
}

// ---------------------------------------------------------------------------
// Warp-MMA 2-pass split-fp16 GEMM: C = A*B^T with A = Ahi+Alo (fp16 pair),
// B = Bhi only. Error ~1e-4 rel per GEMM. CTA 128x128, 8 warps (32x64),
// K chunk 32, cp.async.cg double buffer, ldmatrix fragment loads.
// OUT_SPLIT: 0 -> fp32*scale out, 1 -> split-fp16 out
// CAUSAL_SKIP: skip tiles above diagonal.  KTRUNC: K stops at m0+128 (PV).
// ---------------------------------------------------------------------------
#define GBM 128
#define GBN 128
#define GKC 32
#define SKP 40                       // padded row stride, elems (conflict-free)
#define TILE_BYTES (128 * SKP * 2)   // 10240
#define A_HI_OFF 0
#define A_LO_OFF (TILE_BYTES)
#define B_HI_OFF (2 * TILE_BYTES)
#define BUF_BYTES (3 * TILE_BYTES)   // 30720
#define GSMEM (2 * BUF_BYTES)        // 61440

__device__ __forceinline__ void cp_tile(uint32_t sbase,
        const __half* __restrict__ g, int ld, int row0, int k0, int tid)
{
#pragma unroll
    for (int it = 0; it < 2; ++it) {
        int v = it * 256 + tid;
        int r = v >> 2;
        int c8 = (v & 3) << 3;
        uint32_t dst = sbase + (uint32_t)(r * (SKP * 2) + c8 * 2);
        const void* src = g + (size_t)(row0 + r) * ld + k0 + c8;
        CP_ASYNC16(dst, src);
    }
}

template <int OUT_SPLIT, int CAUSAL_SKIP, int KTRUNC>
__global__ __launch_bounds__(256, 2)
void gemm_mma_kernel(const __half* __restrict__ Ahi_,
                     const __half* __restrict__ Alo_, int lda,
                     const __half* __restrict__ Bhi_, int ldb,
                     int K,
                     float* __restrict__ outF_,
                     __half* __restrict__ outHi_,
                     __half* __restrict__ outLo_, int ldc,
                     size_t sA, size_t sB, size_t sC, float scale)
{
    const int m0 = blockIdx.y * GBM;
    const int n0 = blockIdx.x * GBN;
    if (CAUSAL_SKIP && n0 > m0) return;

    extern __shared__ char smem[];
    const uint32_t sb = smem_to_u32(smem);
    const int tid = threadIdx.x;
    const int w    = tid >> 5;
    const int lane = tid & 31;
    const int group = lane >> 2;
    const int tig   = lane & 3;
    const int wr = w >> 1;                // 0..3 (M)
    const int wc = w & 1;                 // 0..1 (N)
    const int b  = blockIdx.z;

    const __half* Ahi = Ahi_ + (size_t)b * sA;
    const __half* Alo = Alo_ + (size_t)b * sA;
    const __half* Bhi = Bhi_ + (size_t)b * sB;

    const int K_eff = KTRUNC ? (m0 + GBM) : K;
    const int nc = K_eff / GKC;

    // ldmatrix per-lane address components
    const int lq = lane >> 3;
    const int lw = lane & 7;
    const int a_r = lw + ((lq & 1) << 3);
    const int a_c = (lq & 2) << 2;
    const int b_r = lw + ((lq >> 1) << 3);
    const int b_c = (lq & 1) << 3;
    const uint32_t aoff0 = (uint32_t)((wr * 32 + a_r) * SKP + a_c) * 2;
    const uint32_t aoff1 = (uint32_t)((wr * 32 + 16 + a_r) * SKP + a_c) * 2;
    uint32_t boff[4];
#pragma unroll
    for (int ng = 0; ng < 4; ng++)
        boff[ng] = (uint32_t)((wc * 64 + ng * 16 + b_r) * SKP + b_c) * 2;

    float acc[2][8][4];
#pragma unroll
    for (int t = 0; t < 2; t++)
#pragma unroll
        for (int n = 0; n < 8; n++)
#pragma unroll
            for (int j = 0; j < 4; j++) acc[t][n][j] = 0.0f;

    // prologue: chunk 0
    {
        cp_tile(sb + A_HI_OFF, Ahi, lda, m0, 0, tid);
        cp_tile(sb + A_LO_OFF, Alo, lda, m0, 0, tid);
        cp_tile(sb + B_HI_OFF, Bhi, ldb, n0, 0, tid);
        CP_COMMIT();
    }

    for (int c = 0; c < nc; ++c) {
        if (c + 1 < nc) {
            uint32_t buf = sb + ((c + 1) & 1) * BUF_BYTES;
            const int k0 = (c + 1) * GKC;
            cp_tile(buf + A_HI_OFF, Ahi, lda, m0, k0, tid);
            cp_tile(buf + A_LO_OFF, Alo, lda, m0, k0, tid);
            cp_tile(buf + B_HI_OFF, Bhi, ldb, n0, k0, tid);
            CP_COMMIT();
            CP_WAIT(1);
        } else {
            CP_WAIT(0);
        }
        __syncthreads();

        const uint32_t buf = sb + (c & 1) * BUF_BYTES;
#pragma unroll
        for (int kk = 0; kk < GKC; kk += 16) {
            const uint32_t kb = (uint32_t)kk * 2;
            uint32_t ah[2][4], ax[2][4], bb[8][2];

            LDSM_X4(ah[0][0], ah[0][1], ah[0][2], ah[0][3], buf + A_HI_OFF + aoff0 + kb);
            LDSM_X4(ah[1][0], ah[1][1], ah[1][2], ah[1][3], buf + A_HI_OFF + aoff1 + kb);
#pragma unroll
            for (int ng = 0; ng < 4; ng++)
                LDSM_X4(bb[2 * ng][0], bb[2 * ng][1], bb[2 * ng + 1][0], bb[2 * ng + 1][1],
                        buf + B_HI_OFF + boff[ng] + kb);
            // pass 1: Ahi * Bhi
#pragma unroll
            for (int t = 0; t < 2; t++)
#pragma unroll
                for (int n = 0; n < 8; n++)
                    mma16816(acc[t][n], ah[t][0], ah[t][1], ah[t][2], ah[t][3],
                             bb[n][0], bb[n][1]);
            // pass 2: Alo * Bhi
            LDSM_X4(ax[0][0], ax[0][1], ax[0][2], ax[0][3], buf + A_LO_OFF + aoff0 + kb);
            LDSM_X4(ax[1][0], ax[1][1], ax[1][2], ax[1][3], buf + A_LO_OFF + aoff1 + kb);
#pragma unroll
            for (int t = 0; t < 2; t++)
#pragma unroll
                for (int n = 0; n < 8; n++)
                    mma16816(acc[t][n], ax[t][0], ax[t][1], ax[t][2], ax[t][3],
                             bb[n][0], bb[n][1]);
        }
        __syncthreads();
    }

    // Epilogue
#pragma unroll
    for (int t = 0; t < 2; t++) {
        const int row = m0 + wr * 32 + t * 16 + group;
#pragma unroll
        for (int n = 0; n < 8; n++) {
            const int col = n0 + wc * 64 + n * 8 + tig * 2;
            if (OUT_SPLIT == 0) {
                float* dst = outF_ + (size_t)b * sC;
                float2 v0 = make_float2(acc[t][n][0] * scale, acc[t][n][1] * scale);
                float2 v1 = make_float2(acc[t][n][2] * scale, acc[t][n][3] * scale);
                *reinterpret_cast<float2*>(dst + (size_t)row * ldc + col) = v0;
                *reinterpret_cast<float2*>(dst + (size_t)(row + 8) * ldc + col) = v1;
            } else {
                __half* dh = outHi_ + (size_t)b * sC;
                __half* dl = outLo_ + (size_t)b * sC;
#pragma unroll
                for (int hh = 0; hh < 2; hh++) {
                    const int r = row + hh * 8;
                    union { __half x[2]; uint32_t u; } H, L;
                    split_f32(acc[t][n][hh * 2 + 0], H.x[0], L.x[0]);
                    split_f32(acc[t][n][hh * 2 + 1], H.x[1], L.x[1]);
                    *reinterpret_cast<uint32_t*>(dh + (size_t)r * ldc + col) = H.u;
                    *reinterpret_cast<uint32_t*>(dl + (size_t)r * ldc + col) = L.u;
                }
            }
        }
    }
}

// ---------------------------------------------------------------------------
extern "C" void kernel_launch(void* const* d_in, const int* in_sizes, int n_in,
                              void* d_out, int out_size)
{
    const float* x      = (const float*)d_in[0];   // [B,T,C]
    const float* w_qkv  = (const float*)d_in[1];   // [3C,C]
    const float* w_proj = (const float*)d_in[2];   // [C,C]
    float* out = (float*)d_out;                    // [B,T,C]

    __half *xhi, *xlo, *wqhi, *wphi;
    __half *qkvhi, *qkvlo, *phi, *plo, *vthi, *atthi, *attlo;
    float* scores;
    cudaGetSymbolAddress((void**)&xhi, g_xhi);     cudaGetSymbolAddress((void**)&xlo, g_xlo);
    cudaGetSymbolAddress((void**)&wqhi, g_wqhi);   cudaGetSymbolAddress((void**)&wphi, g_wphi);
    cudaGetSymbolAddress((void**)&qkvhi, g_qkvhi); cudaGetSymbolAddress((void**)&qkvlo, g_qkvlo);
    cudaGetSymbolAddress((void**)&scores, g_scores);
    cudaGetSymbolAddress((void**)&phi, g_phi);     cudaGetSymbolAddress((void**)&plo, g_plo);
    cudaGetSymbolAddress((void**)&vthi, g_vthi);
    cudaGetSymbolAddress((void**)&atthi, g_atthi); cudaGetSymbolAddress((void**)&attlo, g_attlo);

    cudaFuncSetAttribute(gemm_mma_kernel<0,0,0>, cudaFuncAttributeMaxDynamicSharedMemorySize, GSMEM);
    cudaFuncSetAttribute(gemm_mma_kernel<1,0,0>, cudaFuncAttributeMaxDynamicSharedMemorySize, GSMEM);
    cudaFuncSetAttribute(gemm_mma_kernel<0,1,0>, cudaFuncAttributeMaxDynamicSharedMemorySize, GSMEM);
    cudaFuncSetAttribute(gemm_mma_kernel<1,0,1>, cudaFuncAttributeMaxDynamicSharedMemorySize, GSMEM);

    const float scale = 1.0f / sqrtf((float)DM);

    // 0) split fp32 inputs to fp16: x needs hi+lo (A-side); weights hi only
    {
        int n4 = (int)(NX / 4);
        split_kernel<<<(n4 + 255) / 256, 256>>>(x, xhi, xlo, n4);
        int w4 = DM3 * DM / 4;
        split_kernel<<<(w4 + 255) / 256, 256>>>(w_qkv, wqhi, nullptr, w4);
        int p4 = DM * DM / 4;
        split_kernel<<<(p4 + 255) / 256, 256>>>(w_proj, wphi, nullptr, p4);
    }

    // 1) qkv = x @ w_qkv^T -> split-fp16
    gemm_mma_kernel<1,0,0><<<dim3(DM3 / GBN, (BATCH * SEQ) / GBM, 1), 256, GSMEM>>>(
        xhi, xlo, DM, wqhi, DM, DM,
        nullptr, qkvhi, qkvlo, DM3, 0, 0, 0, 1.0f);

    // 2) transpose V-hi: vt[b][c][s]
    transpose_v_kernel<<<dim3(SEQ / 32, DM / 32, BATCH), 256>>>(qkvhi, vthi);

    // 3) scores = (Q @ K^T) * scale -> fp32, lower-triangle tiles only
    gemm_mma_kernel<0,1,0><<<dim3(SEQ / GBN, SEQ / GBM, BATCH), 256, GSMEM>>>(
        qkvhi, qkvlo, DM3, qkvhi + DM, DM3, DM,
        scores, nullptr, nullptr, SEQ,
        (size_t)SEQ * DM3, (size_t)SEQ * DM3, (size_t)SEQ * SEQ, scale);

    // 4) causal softmax (valid prefix only) -> split-fp16 P
    softmax_split_kernel<<<BATCH * SEQ, 256>>>(scores, phi, plo);

    // 5) att = P @ V (K truncated causally) -> split-fp16
    gemm_mma_kernel<1,0,1><<<dim3(DM / GBN, SEQ / GBM, BATCH), 256, GSMEM>>>(
        phi, plo, SEQ, vthi, SEQ, SEQ,
        nullptr, atthi, attlo, DM,
        (size_t)SEQ * SEQ, (size_t)DM * SEQ, (size_t)SEQ * DM, 1.0f);

    // 6) out = att @ w_proj^T -> fp32
    gemm_mma_kernel<0,0,0><<<dim3(DM / GBN, (BATCH * SEQ) / GBM, 1), 256, GSMEM>>>(
        atthi, attlo, DM, wphi, DM, DM,
        out, nullptr, nullptr, DM, 0, 0, 0, 1.0f);
}

// round 13
// speedup vs baseline: 3.5885x; 1.0157x over previous
#include <cuda_runtime.h>
#include <cuda_fp16.h>
#include <cstdint>
#include <math.h>

// Problem constants (B=4, T=4096, C=512)
#define BATCH 4
#define SEQ   4096
#define DM    512
#define DM3   1536

// ---------------------------------------------------------------------------
// Scratch (device globals; no allocation allowed)
// ---------------------------------------------------------------------------
#define NX   ((size_t)BATCH * SEQ * DM)
#define NQKV ((size_t)BATCH * SEQ * DM3)
#define NS   ((size_t)BATCH * SEQ * SEQ)

__device__ __half g_xhi[NX],   g_xlo[NX];
__device__ __half g_wqhi[(size_t)DM3 * DM];
__device__ __half g_wphi[(size_t)DM * DM];
__device__ __half g_qkvhi[NQKV], g_qkvlo[NQKV];
__device__ float  g_scores[NS];
__device__ __half g_phi[NS], g_plo[NS];
__device__ __half g_vthi[NX];
__device__ __half g_atthi[NX], g_attlo[NX];

// ---------------------------------------------------------------------------
// PTX helpers
// ---------------------------------------------------------------------------
__device__ __forceinline__ uint32_t smem_to_u32(const void* p) {
    uint32_t a;
    asm("{ .reg .u64 t; cvta.to.shared.u64 t, %1; cvt.u32.u64 %0, t; }"
        : "=r"(a) : "l"(p));
    return a;
}
#define CP_ASYNC16(dst, src) \
    asm volatile("cp.async.cg.shared.global [%0], [%1], 16;" :: "r"(dst), "l"(src))
#define CP_COMMIT() asm volatile("cp.async.commit_group;" ::: "memory")
#define CP_WAIT(n)  asm volatile("cp.async.wait_group %0;" :: "n"(n) : "memory")

#define LDSM_X4(r0, r1, r2, r3, addr) \
    asm volatile("ldmatrix.sync.aligned.m8n8.x4.shared.b16 {%0,%1,%2,%3}, [%4];" \
        : "=r"(r0), "=r"(r1), "=r"(r2), "=r"(r3) : "r"(addr))

__device__ __forceinline__ void mma16816(float* c,
        uint32_t a0, uint32_t a1, uint32_t a2, uint32_t a3,
        uint32_t b0, uint32_t b1) {
    asm volatile(
        "mma.sync.aligned.m16n8k16.row.col.f32.f16.f16.f32 "
        "{%0,%1,%2,%3}, {%4,%5,%6,%7}, {%8,%9}, {%0,%1,%2,%3};"
        : "+f"(c[0]), "+f"(c[1]), "+f"(c[2]), "+f"(c[3])
        : "r"(a0), "r"(a1), "r"(a2), "r"(a3), "r"(b0), "r"(b1));
}

__device__ __forceinline__ void split_f32(float v, __half& h, __half& l) {
    h = __float2half_rn(v);
    l = __float2half_rn(v - __half2float(h));
}

// ---------------------------------------------------------------------------
// fp32 -> (hi, lo) fp16 split (lo optional)
// ---------------------------------------------------------------------------
__global__ __launch_bounds__(256)
void split_kernel(const float* __restrict__ in, __half* __restrict__ hi,
                  __half* __restrict__ lo, int n4)
{
    int i = blockIdx.x * 256 + threadIdx.x;
    if (i >= n4) return;
    float4 v = reinterpret_cast<const float4*>(in)[i];
    float a[4] = {v.x, v.y, v.z, v.w};
    union { __half h[4]; uint2 u; } H, L;
#pragma unroll
    for (int j = 0; j < 4; j++) split_f32(a[j], H.h[j], L.h[j]);
    reinterpret_cast<uint2*>(hi)[i] = H.u;
    if (lo) reinterpret_cast<uint2*>(lo)[i] = L.u;
}

// ---------------------------------------------------------------------------
// Transpose V-hi slice of qkv: vt[b][c][s] = qkvhi[b*SEQ + s][2*DM + c]
// ---------------------------------------------------------------------------
__global__ __launch_bounds__(256)
void transpose_v_kernel(const __half* __restrict__ qhi,
                        __half* __restrict__ vthi)
{
    __shared__ __half t[32][33];
    const int b  = blockIdx.z;
    const int s0 = blockIdx.x * 32;
    const int c0 = blockIdx.y * 32;
    const int tx = threadIdx.x & 31;
    const int ty = threadIdx.x >> 5;
#pragma unroll
    for (int j = 0; j < 4; j++) {
        int s = s0 + ty + 8 * j;
        t[ty + 8 * j][tx] = qhi[((size_t)b * SEQ + s) * DM3 + 2 * DM + c0 + tx];
    }
    __syncthreads();
#pragma unroll
    for (int j = 0; j < 4; j++) {
        int c = c0 + ty + 8 * j;
        vthi[(size_t)b * DM * SEQ + (size_t)c * SEQ + s0 + tx] = t[tx][ty + 8 * j];
    }
}

// ---------------------------------------------------------------------------
// Causal softmax over valid prefix only -> split-fp16 P (+zeros to tile end)
// ---------------------------------------------------------------------------
__global__ __launch_bounds__(256)
void softmax_split_kernel(const float* __restrict__ S,
                          __half* __restrict__ phi,
                          __half* __restrict__ plo)
{
    __shared__ float e[SEQ];
    __shared__ float redm[8], reds[8];
    const size_t row = blockIdx.x;
    const int t = (int)(row & (SEQ - 1));
    const int nval = t + 1;
    const int tile_end = ((t >> 7) + 1) << 7;
    const float* p = S + row * (size_t)SEQ;
    const int tid = threadIdx.x;

    float m = -INFINITY;
    for (int i = tid; i < nval; i += 256) m = fmaxf(m, p[i]);
#pragma unroll
    for (int o = 16; o > 0; o >>= 1)
        m = fmaxf(m, __shfl_xor_sync(0xffffffffu, m, o));
    if ((tid & 31) == 0) redm[tid >> 5] = m;
    __syncthreads();
    m = fmaxf(fmaxf(fmaxf(redm[0], redm[1]), fmaxf(redm[2], redm[3])),
              fmaxf(fmaxf(redm[4], redm[5]), fmaxf(redm[6], redm[7])));

    float s = 0.0f;
    for (int i = tid; i < nval; i += 256) {
        float ev = __expf(p[i] - m);
        e[i] = ev;
        s += ev;
    }
#pragma unroll
    for (int o = 16; o > 0; o >>= 1)
        s += __shfl_xor_sync(0xffffffffu, s, o);
    if ((tid & 31) == 0) reds[tid >> 5] = s;
    __syncthreads();
    s = reds[0] + reds[1] + reds[2] + reds[3] +
        reds[4] + reds[5] + reds[6] + reds[7];

    const float inv = 1.0f / s;
    for (int i = tid; i < tile_end; i += 256) {
        float w = (i < nval) ? e[i] * inv : 0.0f;
        __half h, l;
        split_f32(w, h, l);
        size_t o = row * (size_t)SEQ + i;
        phi[o] = h; plo[o] = l;
    }
}

// ---------------------------------------------------------------------------
// Warp-MMA 2-pass split-fp16 GEMM, 3-stage cp.async pipeline, 1 sync/chunk.
// C = (Ahi+Alo) * Bhi^T, fp32 accumulate. CTA 128x128, 8 warps (32x64 each),
// K chunk 32, ldmatrix fragment loads (all hoisted ahead of the MMA stream).
// ---------------------------------------------------------------------------
#define GBM 128
#define GBN 128
#define GKC 32
#define NSTAGE 3
#define SKP 40                       // padded row stride, elems (conflict-free)
#define TILE_BYTES (128 * SKP * 2)   // 10240
#define A_HI_OFF 0
#define A_LO_OFF (TILE_BYTES)
#define B_HI_OFF (2 * TILE_BYTES)
#define BUF_BYTES (3 * TILE_BYTES)   // 30720
#define GSMEM (NSTAGE * BUF_BYTES)   // 92160

__device__ __forceinline__ void cp_tile(uint32_t sbase,
        const __half* __restrict__ g, int ld, int row0, int k0, int tid)
{
#pragma unroll
    for (int it = 0; it < 2; ++it) {
        int v = it * 256 + tid;
        int r = v >> 2;
        int c8 = (v & 3) << 3;
        uint32_t dst = sbase + (uint32_t)(r * (SKP * 2) + c8 * 2);
        const void* src = g + (size_t)(row0 + r) * ld + k0 + c8;
        CP_ASYNC16(dst, src);
    }
}

template <int OUT_SPLIT, int CAUSAL_SKIP, int KTRUNC>
__global__ __launch_bounds__(256, 2)
void gemm_mma_kernel(const __half* __restrict__ Ahi_,
                     const __half* __restrict__ Alo_, int lda,
                     const __half* __restrict__ Bhi_, int ldb,
                     int K,
                     float* __restrict__ outF_,
                     __half* __restrict__ outHi_,
                     __half* __restrict__ outLo_, int ldc,
                     size_t sA, size_t sB, size_t sC, float scale)
{
    const int m0 = blockIdx.y * GBM;
    const int n0 = blockIdx.x * GBN;
    if (CAUSAL_SKIP && n0 > m0) return;

    extern __shared__ char smem[];
    const uint32_t sb = smem_to_u32(smem);
    const int tid = threadIdx.x;
    const int w    = tid >> 5;
    const int lane = tid & 31;
    const int group = lane >> 2;
    const int tig   = lane & 3;
    const int wr = w >> 1;                // 0..3 (M)
    const int wc = w & 1;                 // 0..1 (N)
    const int b  = blockIdx.z;

    const __half* Ahi = Ahi_ + (size_t)b * sA;
    const __half* Alo = Alo_ + (size_t)b * sA;
    const __half* Bhi = Bhi_ + (size_t)b * sB;

    const int K_eff = KTRUNC ? (m0 + GBM) : K;
    const int nc = K_eff / GKC;           // >= 4 always

    // ldmatrix per-lane address components
    const int lq = lane >> 3;
    const int lw = lane & 7;
    const int a_r = lw + ((lq & 1) << 3);
    const int a_c = (lq & 2) << 2;
    const int b_r = lw + ((lq >> 1) << 3);
    const int b_c = (lq & 1) << 3;
    const uint32_t aoff0 = (uint32_t)((wr * 32 + a_r) * SKP + a_c) * 2;
    const uint32_t aoff1 = (uint32_t)((wr * 32 + 16 + a_r) * SKP + a_c) * 2;
    uint32_t boff[4];
#pragma unroll
    for (int ng = 0; ng < 4; ng++)
        boff[ng] = (uint32_t)((wc * 64 + ng * 16 + b_r) * SKP + b_c) * 2;

    float acc[2][8][4];
#pragma unroll
    for (int t = 0; t < 2; t++)
#pragma unroll
        for (int n = 0; n < 8; n++)
#pragma unroll
            for (int j = 0; j < 4; j++) acc[t][n][j] = 0.0f;

    // prologue: load chunks 0 and 1 into stages 0, 1 (one commit group each)
    cp_tile(sb + A_HI_OFF, Ahi, lda, m0, 0, tid);
    cp_tile(sb + A_LO_OFF, Alo, lda, m0, 0, tid);
    cp_tile(sb + B_HI_OFF, Bhi, ldb, n0, 0, tid);
    CP_COMMIT();
    cp_tile(sb + BUF_BYTES + A_HI_OFF, Ahi, lda, m0, GKC, tid);
    cp_tile(sb + BUF_BYTES + A_LO_OFF, Alo, lda, m0, GKC, tid);
    cp_tile(sb + BUF_BYTES + B_HI_OFF, Bhi, ldb, n0, GKC, tid);
    CP_COMMIT();

    int stage = 0;
    for (int c = 0; c < nc; ++c) {
        CP_WAIT(1);                 // chunk c complete (c+1 may be in flight)
        __syncthreads();            // also: everyone done reading stage of c-1

        if (c + 2 < nc) {           // prefetch chunk c+2 into the freed stage
            int ps = stage + 2; if (ps >= NSTAGE) ps -= NSTAGE;
            uint32_t buf = sb + ps * BUF_BYTES;
            const int k0 = (c + 2) * GKC;
            cp_tile(buf + A_HI_OFF, Ahi, lda, m0, k0, tid);
            cp_tile(buf + A_LO_OFF, Alo, lda, m0, k0, tid);
            cp_tile(buf + B_HI_OFF, Bhi, ldb, n0, k0, tid);
        }
        CP_COMMIT();                // commit every iteration (may be empty)

        const uint32_t buf = sb + stage * BUF_BYTES;
#pragma unroll
        for (int kk = 0; kk < GKC; kk += 16) {
            const uint32_t kb = (uint32_t)kk * 2;
            uint32_t ah[2][4], ax[2][4], bb[8][2];

            // hoist ALL fragment loads ahead of the MMA stream
            LDSM_X4(ah[0][0], ah[0][1], ah[0][2], ah[0][3], buf + A_HI_OFF + aoff0 + kb);
            LDSM_X4(ah[1][0], ah[1][1], ah[1][2], ah[1][3], buf + A_HI_OFF + aoff1 + kb);
            LDSM_X4(ax[0][0], ax[0][1], ax[0][2], ax[0][3], buf + A_LO_OFF + aoff0 + kb);
            LDSM_X4(ax[1][0], ax[1][1], ax[1][2], ax[1][3], buf + A_LO_OFF + aoff1 + kb);
#pragma unroll
            for (int ng = 0; ng < 4; ng++)
                LDSM_X4(bb[2 * ng][0], bb[2 * ng][1], bb[2 * ng + 1][0], bb[2 * ng + 1][1],
                        buf + B_HI_OFF + boff[ng] + kb);

            // pass 1: Ahi * Bhi
#pragma unroll
            for (int t = 0; t < 2; t++)
#pragma unroll
                for (int n = 0; n < 8; n++)
                    mma16816(acc[t][n], ah[t][0], ah[t][1], ah[t][2], ah[t][3],
                             bb[n][0], bb[n][1]);
            // pass 2: Alo * Bhi
#pragma unroll
            for (int t = 0; t < 2; t++)
#pragma unroll
                for (int n = 0; n < 8; n++)
                    mma16816(acc[t][n], ax[t][0], ax[t][1], ax[t][2], ax[t][3],
                             bb[n][0], bb[n][1]);
        }
        if (++stage >= NSTAGE) stage = 0;
    }

    // Epilogue
#pragma unroll
    for (int t = 0; t < 2; t++) {
        const int row = m0 + wr * 32 + t * 16 + group;
#pragma unroll
        for (int n = 0; n < 8; n++) {
            const int col = n0 + wc * 64 + n * 8 + tig * 2;
            if (OUT_SPLIT == 0) {
                float* dst = outF_ + (size_t)b * sC;
                float2 v0 = make_float2(acc[t][n][0] * scale, acc[t][n][1] * scale);
                float2 v1 = make_float2(acc[t][n][2] * scale, acc[t][n][3] * scale);
                *reinterpret_cast<float2*>(dst + (size_t)row * ldc + col) = v0;
                *reinterpret_cast<float2*>(dst + (size_t)(row + 8) * ldc + col) = v1;
            } else {
                __half* dh = outHi_ + (size_t)b * sC;
                __half* dl = outLo_ + (size_t)b * sC;
#pragma unroll
                for (int hh = 0; hh < 2; hh++) {
                    const int r = row + hh * 8;
                    union { __half x[2]; uint32_t u; } H, L;
                    split_f32(acc[t][n][hh * 2 + 0], H.x[0], L.x[0]);
                    split_f32(acc[t][n][hh * 2 + 1], H.x[1], L.x[1]);
                    *reinterpret_cast<uint32_t*>(dh + (size_t)r * ldc + col) = H.u;
                    *reinterpret_cast<uint32_t*>(dl + (size_t)r * ldc + col) = L.u;
                }
            }
        }
    }
}

// ---------------------------------------------------------------------------
extern "C" void kernel_launch(void* const* d_in, const int* in_sizes, int n_in,
                              void* d_out, int out_size)
{
    const float* x      = (const float*)d_in[0];   // [B,T,C]
    const float* w_qkv  = (const float*)d_in[1];   // [3C,C]
    const float* w_proj = (const float*)d_in[2];   // [C,C]
    float* out = (float*)d_out;                    // [B,T,C]

    __half *xhi, *xlo, *wqhi, *wphi;
    __half *qkvhi, *qkvlo, *phi, *plo, *vthi, *atthi, *attlo;
    float* scores;
    cudaGetSymbolAddress((void**)&xhi, g_xhi);     cudaGetSymbolAddress((void**)&xlo, g_xlo);
    cudaGetSymbolAddress((void**)&wqhi, g_wqhi);   cudaGetSymbolAddress((void**)&wphi, g_wphi);
    cudaGetSymbolAddress((void**)&qkvhi, g_qkvhi); cudaGetSymbolAddress((void**)&qkvlo, g_qkvlo);
    cudaGetSymbolAddress((void**)&scores, g_scores);
    cudaGetSymbolAddress((void**)&phi, g_phi);     cudaGetSymbolAddress((void**)&plo, g_plo);
    cudaGetSymbolAddress((void**)&vthi, g_vthi);
    cudaGetSymbolAddress((void**)&atthi, g_atthi); cudaGetSymbolAddress((void**)&attlo, g_attlo);

    cudaFuncSetAttribute(gemm_mma_kernel<0,0,0>, cudaFuncAttributeMaxDynamicSharedMemorySize, GSMEM);
    cudaFuncSetAttribute(gemm_mma_kernel<1,0,0>, cudaFuncAttributeMaxDynamicSharedMemorySize, GSMEM);
    cudaFuncSetAttribute(gemm_mma_kernel<0,1,0>, cudaFuncAttributeMaxDynamicSharedMemorySize, GSMEM);
    cudaFuncSetAttribute(gemm_mma_kernel<1,0,1>, cudaFuncAttributeMaxDynamicSharedMemorySize, GSMEM);

    const float scale = 1.0f / sqrtf((float)DM);

    // 0) split fp32 inputs to fp16: x needs hi+lo (A-side); weights hi only
    {
        int n4 = (int)(NX / 4);
        split_kernel<<<(n4 + 255) / 256, 256>>>(x, xhi, xlo, n4);
        int w4 = DM3 * DM / 4;
        split_kernel<<<(w4 + 255) / 256, 256>>>(w_qkv, wqhi, nullptr, w4);
        int p4 = DM * DM / 4;
        split_kernel<<<(p4 + 255) / 256, 256>>>(w_proj, wphi, nullptr, p4);
    }

    // 1) qkv = x @ w_qkv^T -> split-fp16
    gemm_mma_kernel<1,0,0><<<dim3(DM3 / GBN, (BATCH * SEQ) / GBM, 1), 256, GSMEM>>>(
        xhi, xlo, DM, wqhi, DM, DM,
        nullptr, qkvhi, qkvlo, DM3, 0, 0, 0, 1.0f);

    // 2) transpose V-hi: vt[b][c][s]
    transpose_v_kernel<<<dim3(SEQ / 32, DM / 32, BATCH), 256>>>(qkvhi, vthi);

    // 3) scores = (Q @ K^T) * scale -> fp32, lower-triangle tiles only
    gemm_mma_kernel<0,1,0><<<dim3(SEQ / GBN, SEQ / GBM, BATCH), 256, GSMEM>>>(
        qkvhi, qkvlo, DM3, qkvhi + DM, DM3, DM,
        scores, nullptr, nullptr, SEQ,
        (size_t)SEQ * DM3, (size_t)SEQ * DM3, (size_t)SEQ * SEQ, scale);

    // 4) causal softmax (valid prefix only) -> split-fp16 P
    softmax_split_kernel<<<BATCH * SEQ, 256>>>(scores, phi, plo);

    // 5) att = P @ V (K truncated causally) -> split-fp16
    gemm_mma_kernel<1,0,1><<<dim3(DM / GBN, SEQ / GBM, BATCH), 256, GSMEM>>>(
        phi, plo, SEQ, vthi, SEQ, SEQ,
        nullptr, atthi, attlo, DM,
        (size_t)SEQ * SEQ, (size_t)DM * SEQ, (size_t)SEQ * DM, 1.0f);

    // 6) out = att @ w_proj^T -> fp32
    gemm_mma_kernel<0,0,0><<<dim3(DM / GBN, (BATCH * SEQ) / GBM, 1), 256, GSMEM>>>(
        atthi, attlo, DM, wphi, DM, DM,
        out, nullptr, nullptr, DM, 0, 0, 0, 1.0f);
}

// round 14
// speedup vs baseline: 5.1171x; 1.4260x over previous
#include <cuda_runtime.h>
#include <cuda_fp16.h>
#include <cstdint>
#include <math.h>

// Problem constants (B=4, T=4096, C=512)
#define BATCH 4
#define SEQ   4096
#define DM    512
#define DM3   1536

// ---------------------------------------------------------------------------
// Scratch (device globals; no allocation allowed)
// ---------------------------------------------------------------------------
#define NX   ((size_t)BATCH * SEQ * DM)
#define NQKV ((size_t)BATCH * SEQ * DM3)
#define NS   ((size_t)BATCH * SEQ * SEQ)

__device__ __half g_xhi[NX],   g_xlo[NX];
__device__ __half g_wqhi[(size_t)DM3 * DM];
__device__ __half g_wphi[(size_t)DM * DM];
__device__ __half g_qkvhi[NQKV];
__device__ float  g_scores[NS];
__device__ __half g_phi[NS];
__device__ __half g_vthi[NX];
__device__ __half g_atthi[NX], g_attlo[NX];

// ---------------------------------------------------------------------------
// PTX helpers
// ---------------------------------------------------------------------------
__device__ __forceinline__ uint32_t smem_to_u32(const void* p) {
    uint32_t a;
    asm("{ .reg .u64 t; cvta.to.shared.u64 t, %1; cvt.u32.u64 %0, t; }"
        : "=r"(a) : "l"(p));
    return a;
}
#define CP_ASYNC16(dst, src) \
    asm volatile("cp.async.cg.shared.global [%0], [%1], 16;" :: "r"(dst), "l"(src))
#define CP_COMMIT() asm volatile("cp.async.commit_group;" ::: "memory")
#define CP_WAIT(n)  asm volatile("cp.async.wait_group %0;" :: "n"(n) : "memory")

#define LDSM_X4(r0, r1, r2, r3, addr) \
    asm volatile("ldmatrix.sync.aligned.m8n8.x4.shared.b16 {%0,%1,%2,%3}, [%4];" \
        : "=r"(r0), "=r"(r1), "=r"(r2), "=r"(r3) : "r"(addr))

__device__ __forceinline__ void mma16816(float* c,
        uint32_t a0, uint32_t a1, uint32_t a2, uint32_t a3,
        uint32_t b0, uint32_t b1) {
    asm volatile(
        "mma.sync.aligned.m16n8k16.row.col.f32.f16.f16.f32 "
        "{%0,%1,%2,%3}, {%4,%5,%6,%7}, {%8,%9}, {%0,%1,%2,%3};"
        : "+f"(c[0]), "+f"(c[1]), "+f"(c[2]), "+f"(c[3])
        : "r"(a0), "r"(a1), "r"(a2), "r"(a3), "r"(b0), "r"(b1));
}

__device__ __forceinline__ void split_f32(float v, __half& h, __half& l) {
    h = __float2half_rn(v);
    l = __float2half_rn(v - __half2float(h));
}

// ---------------------------------------------------------------------------
// fp32 -> (hi, lo) fp16 split (lo optional)
// ---------------------------------------------------------------------------
__global__ __launch_bounds__(256)
void split_kernel(const float* __restrict__ in, __half* __restrict__ hi,
                  __half* __restrict__ lo, int n4)
{
    int i = blockIdx.x * 256 + threadIdx.x;
    if (i >= n4) return;
    float4 v = reinterpret_cast<const float4*>(in)[i];
    float a[4] = {v.x, v.y, v.z, v.w};
    union { __half h[4]; uint2 u; } H, L;
#pragma unroll
    for (int j = 0; j < 4; j++) split_f32(a[j], H.h[j], L.h[j]);
    reinterpret_cast<uint2*>(hi)[i] = H.u;
    if (lo) reinterpret_cast<uint2*>(lo)[i] = L.u;
}

// ---------------------------------------------------------------------------
// Transpose V-hi slice of qkv: vt[b][c][s] = qkvhi[b*SEQ + s][2*DM + c]
// ---------------------------------------------------------------------------
__global__ __launch_bounds__(256)
void transpose_v_kernel(const __half* __restrict__ qhi,
                        __half* __restrict__ vthi)
{
    __shared__ __half t[32][33];
    const int b  = blockIdx.z;
    const int s0 = blockIdx.x * 32;
    const int c0 = blockIdx.y * 32;
    const int tx = threadIdx.x & 31;
    const int ty = threadIdx.x >> 5;
#pragma unroll
    for (int j = 0; j < 4; j++) {
        int s = s0 + ty + 8 * j;
        t[ty + 8 * j][tx] = qhi[((size_t)b * SEQ + s) * DM3 + 2 * DM + c0 + tx];
    }
    __syncthreads();
#pragma unroll
    for (int j = 0; j < 4; j++) {
        int c = c0 + ty + 8 * j;
        vthi[(size_t)b * DM * SEQ + (size_t)c * SEQ + s0 + tx] = t[tx][ty + 8 * j];
    }
}

// ---------------------------------------------------------------------------
// Causal softmax over valid prefix only -> fp16 P-hi (+zeros to tile end)
// ---------------------------------------------------------------------------
__global__ __launch_bounds__(256)
void softmax_kernel(const float* __restrict__ S, __half* __restrict__ phi)
{
    __shared__ float e[SEQ];
    __shared__ float redm[8], reds[8];
    const size_t row = blockIdx.x;
    const int t = (int)(row & (SEQ - 1));
    const int nval = t + 1;
    const int tile_end = ((t >> 7) + 1) << 7;
    const float* p = S + row * (size_t)SEQ;
    const int tid = threadIdx.x;

    float m = -INFINITY;
    for (int i = tid; i < nval; i += 256) m = fmaxf(m, p[i]);
#pragma unroll
    for (int o = 16; o > 0; o >>= 1)
        m = fmaxf(m, __shfl_xor_sync(0xffffffffu, m, o));
    if ((tid & 31) == 0) redm[tid >> 5] = m;
    __syncthreads();
    m = fmaxf(fmaxf(fmaxf(redm[0], redm[1]), fmaxf(redm[2], redm[3])),
              fmaxf(fmaxf(redm[4], redm[5]), fmaxf(redm[6], redm[7])));

    float s = 0.0f;
    for (int i = tid; i < nval; i += 256) {
        float ev = __expf(p[i] - m);
        e[i] = ev;
        s += ev;
    }
#pragma unroll
    for (int o = 16; o > 0; o >>= 1)
        s += __shfl_xor_sync(0xffffffffu, s, o);
    if ((tid & 31) == 0) reds[tid >> 5] = s;
    __syncthreads();
    s = reds[0] + reds[1] + reds[2] + reds[3] +
        reds[4] + reds[5] + reds[6] + reds[7];

    const float inv = 1.0f / s;
    for (int i = tid; i < tile_end; i += 256) {
        float w = (i < nval) ? e[i] * inv : 0.0f;
        phi[row * (size_t)SEQ + i] = __float2half_rn(w);
    }
}

// ---------------------------------------------------------------------------
// Warp-MMA split-fp16 GEMM, 3-stage cp.async pipeline, 1 sync/chunk.
// TWO_PASS=1: C = (Ahi+Alo)*Bhi^T (two MMA passes); TWO_PASS=0: C = Ahi*Bhi^T.
// OUT: 0 -> fp32*scale, 1 -> split-fp16 (hi+lo), 2 -> fp16 hi only.
// CTA 128x128, 8 warps (32x64 each), K chunk 32, ldmatrix fragment loads.
// CAUSAL_SKIP: skip tiles above diagonal.  KTRUNC: K stops at m0+128 (PV).
// ---------------------------------------------------------------------------
#define GBM 128
#define GBN 128
#define GKC 32
#define NSTAGE 3
#define SKP 40                       // padded row stride, elems (conflict-free)
#define TILE_BYTES (128 * SKP * 2)   // 10240
#define A_HI_OFF 0
#define A_LO_OFF (TILE_BYTES)
#define B_HI_OFF (2 * TILE_BYTES)
#define BUF_BYTES (3 * TILE_BYTES)   // 30720
#define GSMEM (NSTAGE * BUF_BYTES)   // 92160

__device__ __forceinline__ void cp_tile(uint32_t sbase,
        const __half* __restrict__ g, int ld, int row0, int k0, int tid)
{
#pragma unroll
    for (int it = 0; it < 2; ++it) {
        int v = it * 256 + tid;
        int r = v >> 2;
        int c8 = (v & 3) << 3;
        uint32_t dst = sbase + (uint32_t)(r * (SKP * 2) + c8 * 2);
        const void* src = g + (size_t)(row0 + r) * ld + k0 + c8;
        CP_ASYNC16(dst, src);
    }
}

template <int OUT, int TWO_PASS, int CAUSAL_SKIP, int KTRUNC>
__global__ __launch_bounds__(256, 2)
void gemm_mma_kernel(const __half* __restrict__ Ahi_,
                     const __half* __restrict__ Alo_, int lda,
                     const __half* __restrict__ Bhi_, int ldb,
                     int K,
                     float* __restrict__ outF_,
                     __half* __restrict__ outHi_,
                     __half* __restrict__ outLo_, int ldc,
                     size_t sA, size_t sB, size_t sC, float scale)
{
    const int m0 = blockIdx.y * GBM;
    const int n0 = blockIdx.x * GBN;
    if (CAUSAL_SKIP && n0 > m0) return;

    extern __shared__ char smem[];
    const uint32_t sb = smem_to_u32(smem);
    const int tid = threadIdx.x;
    const int w    = tid >> 5;
    const int lane = tid & 31;
    const int group = lane >> 2;
    const int tig   = lane & 3;
    const int wr = w >> 1;                // 0..3 (M)
    const int wc = w & 1;                 // 0..1 (N)
    const int b  = blockIdx.z;

    const __half* Ahi = Ahi_ + (size_t)b * sA;
    const __half* Alo = TWO_PASS ? (Alo_ + (size_t)b * sA) : nullptr;
    const __half* Bhi = Bhi_ + (size_t)b * sB;

    const int K_eff = KTRUNC ? (m0 + GBM) : K;
    const int nc = K_eff / GKC;           // >= 4 always

    // ldmatrix per-lane address components
    const int lq = lane >> 3;
    const int lw = lane & 7;
    const int a_r = lw + ((lq & 1) << 3);
    const int a_c = (lq & 2) << 2;
    const int b_r = lw + ((lq >> 1) << 3);
    const int b_c = (lq & 1) << 3;
    const uint32_t aoff0 = (uint32_t)((wr * 32 + a_r) * SKP + a_c) * 2;
    const uint32_t aoff1 = (uint32_t)((wr * 32 + 16 + a_r) * SKP + a_c) * 2;
    uint32_t boff[4];
#pragma unroll
    for (int ng = 0; ng < 4; ng++)
        boff[ng] = (uint32_t)((wc * 64 + ng * 16 + b_r) * SKP + b_c) * 2;

    float acc[2][8][4];
#pragma unroll
    for (int t = 0; t < 2; t++)
#pragma unroll
        for (int n = 0; n < 8; n++)
#pragma unroll
            for (int j = 0; j < 4; j++) acc[t][n][j] = 0.0f;

    // prologue: load chunks 0 and 1 into stages 0, 1
    cp_tile(sb + A_HI_OFF, Ahi, lda, m0, 0, tid);
    if (TWO_PASS) cp_tile(sb + A_LO_OFF, Alo, lda, m0, 0, tid);
    cp_tile(sb + B_HI_OFF, Bhi, ldb, n0, 0, tid);
    CP_COMMIT();
    cp_tile(sb + BUF_BYTES + A_HI_OFF, Ahi, lda, m0, GKC, tid);
    if (TWO_PASS) cp_tile(sb + BUF_BYTES + A_LO_OFF, Alo, lda, m0, GKC, tid);
    cp_tile(sb + BUF_BYTES + B_HI_OFF, Bhi, ldb, n0, GKC, tid);
    CP_COMMIT();

    int stage = 0;
    for (int c = 0; c < nc; ++c) {
        CP_WAIT(1);                 // chunk c complete (c+1 may be in flight)
        __syncthreads();            // everyone done reading stage of c-1

        if (c + 2 < nc) {           // prefetch chunk c+2 into the freed stage
            int ps = stage + 2; if (ps >= NSTAGE) ps -= NSTAGE;
            uint32_t buf = sb + ps * BUF_BYTES;
            const int k0 = (c + 2) * GKC;
            cp_tile(buf + A_HI_OFF, Ahi, lda, m0, k0, tid);
            if (TWO_PASS) cp_tile(buf + A_LO_OFF, Alo, lda, m0, k0, tid);
            cp_tile(buf + B_HI_OFF, Bhi, ldb, n0, k0, tid);
        }
        CP_COMMIT();                // commit every iteration (may be empty)

        const uint32_t buf = sb + stage * BUF_BYTES;
#pragma unroll
        for (int kk = 0; kk < GKC; kk += 16) {
            const uint32_t kb = (uint32_t)kk * 2;
            uint32_t ah[2][4], bb[8][2];

            LDSM_X4(ah[0][0], ah[0][1], ah[0][2], ah[0][3], buf + A_HI_OFF + aoff0 + kb);
            LDSM_X4(ah[1][0], ah[1][1], ah[1][2], ah[1][3], buf + A_HI_OFF + aoff1 + kb);
#pragma unroll
            for (int ng = 0; ng < 4; ng++)
                LDSM_X4(bb[2 * ng][0], bb[2 * ng][1], bb[2 * ng + 1][0], bb[2 * ng + 1][1],
                        buf + B_HI_OFF + boff[ng] + kb);

            // pass 1: Ahi * Bhi
#pragma unroll
            for (int t = 0; t < 2; t++)
#pragma unroll
                for (int n = 0; n < 8; n++)
                    mma16816(acc[t][n], ah[t][0], ah[t][1], ah[t][2], ah[t][3],
                             bb[n][0], bb[n][1]);
            // pass 2: Alo * Bhi (only when TWO_PASS)
            if (TWO_PASS) {
                uint32_t ax[2][4];
                LDSM_X4(ax[0][0], ax[0][1], ax[0][2], ax[0][3], buf + A_LO_OFF + aoff0 + kb);
                LDSM_X4(ax[1][0], ax[1][1], ax[1][2], ax[1][3], buf + A_LO_OFF + aoff1 + kb);
#pragma unroll
                for (int t = 0; t < 2; t++)
#pragma unroll
                    for (int n = 0; n < 8; n++)
                        mma16816(acc[t][n], ax[t][0], ax[t][1], ax[t][2], ax[t][3],
                                 bb[n][0], bb[n][1]);
            }
        }
        if (++stage >= NSTAGE) stage = 0;
    }

    // Epilogue
#pragma unroll
    for (int t = 0; t < 2; t++) {
        const int row = m0 + wr * 32 + t * 16 + group;
#pragma unroll
        for (int n = 0; n < 8; n++) {
            const int col = n0 + wc * 64 + n * 8 + tig * 2;
            if (OUT == 0) {
                float* dst = outF_ + (size_t)b * sC;
                float2 v0 = make_float2(acc[t][n][0] * scale, acc[t][n][1] * scale);
                float2 v1 = make_float2(acc[t][n][2] * scale, acc[t][n][3] * scale);
                *reinterpret_cast<float2*>(dst + (size_t)row * ldc + col) = v0;
                *reinterpret_cast<float2*>(dst + (size_t)(row + 8) * ldc + col) = v1;
            } else if (OUT == 1) {
                __half* dh = outHi_ + (size_t)b * sC;
                __half* dl = outLo_ + (size_t)b * sC;
#pragma unroll
                for (int hh = 0; hh < 2; hh++) {
                    const int r = row + hh * 8;
                    union { __half x[2]; uint32_t u; } H, L;
                    split_f32(acc[t][n][hh * 2 + 0], H.x[0], L.x[0]);
                    split_f32(acc[t][n][hh * 2 + 1], H.x[1], L.x[1]);
                    *reinterpret_cast<uint32_t*>(dh + (size_t)r * ldc + col) = H.u;
                    *reinterpret_cast<uint32_t*>(dl + (size_t)r * ldc + col) = L.u;
                }
            } else {   // OUT == 2: hi only
                __half* dh = outHi_ + (size_t)b * sC;
#pragma unroll
                for (int hh = 0; hh < 2; hh++) {
                    const int r = row + hh * 8;
                    union { __half x[2]; uint32_t u; } H;
                    H.x[0] = __float2half_rn(acc[t][n][hh * 2 + 0]);
                    H.x[1] = __float2half_rn(acc[t][n][hh * 2 + 1]);
                    *reinterpret_cast<uint32_t*>(dh + (size_t)r * ldc + col) = H.u;
                }
            }
        }
    }
}

// ---------------------------------------------------------------------------
extern "C" void kernel_launch(void* const* d_in, const int* in_sizes, int n_in,
                              void* d_out, int out_size)
{
    const float* x      = (const float*)d_in[0];   // [B,T,C]
    const float* w_qkv  = (const float*)d_in[1];   // [3C,C]
    const float* w_proj = (const float*)d_in[2];   // [C,C]
    float* out = (float*)d_out;                    // [B,T,C]

    __half *xhi, *xlo, *wqhi, *wphi;
    __half *qkvhi, *phi, *vthi, *atthi, *attlo;
    float* scores;
    cudaGetSymbolAddress((void**)&xhi, g_xhi);     cudaGetSymbolAddress((void**)&xlo, g_xlo);
    cudaGetSymbolAddress((void**)&wqhi, g_wqhi);   cudaGetSymbolAddress((void**)&wphi, g_wphi);
    cudaGetSymbolAddress((void**)&qkvhi, g_qkvhi);
    cudaGetSymbolAddress((void**)&scores, g_scores);
    cudaGetSymbolAddress((void**)&phi, g_phi);
    cudaGetSymbolAddress((void**)&vthi, g_vthi);
    cudaGetSymbolAddress((void**)&atthi, g_atthi); cudaGetSymbolAddress((void**)&attlo, g_attlo);

    cudaFuncSetAttribute(gemm_mma_kernel<2,1,0,0>, cudaFuncAttributeMaxDynamicSharedMemorySize, GSMEM);
    cudaFuncSetAttribute(gemm_mma_kernel<0,0,1,0>, cudaFuncAttributeMaxDynamicSharedMemorySize, GSMEM);
    cudaFuncSetAttribute(gemm_mma_kernel<1,0,0,1>, cudaFuncAttributeMaxDynamicSharedMemorySize, GSMEM);
    cudaFuncSetAttribute(gemm_mma_kernel<0,1,0,0>, cudaFuncAttributeMaxDynamicSharedMemorySize, GSMEM);

    const float scale = 1.0f / sqrtf((float)DM);

    // 0) split fp32 inputs to fp16: x needs hi+lo (A-side); weights hi only
    {
        int n4 = (int)(NX / 4);
        split_kernel<<<(n4 + 255) / 256, 256>>>(x, xhi, xlo, n4);
        int w4 = DM3 * DM / 4;
        split_kernel<<<(w4 + 255) / 256, 256>>>(w_qkv, wqhi, nullptr, w4);
        int p4 = DM * DM / 4;
        split_kernel<<<(p4 + 255) / 256, 256>>>(w_proj, wphi, nullptr, p4);
    }

    // 1) qkv = x @ w_qkv^T (2-pass) -> fp16 hi only
    gemm_mma_kernel<2,1,0,0><<<dim3(DM3 / GBN, (BATCH * SEQ) / GBM, 1), 256, GSMEM>>>(
        xhi, xlo, DM, wqhi, DM, DM,
        nullptr, qkvhi, nullptr, DM3, 0, 0, 0, 1.0f);

    // 2) transpose V-hi: vt[b][c][s]
    transpose_v_kernel<<<dim3(SEQ / 32, DM / 32, BATCH), 256>>>(qkvhi, vthi);

    // 3) scores = (Qhi @ Khi^T) * scale (1-pass) -> fp32, lower tiles only
    gemm_mma_kernel<0,0,1,0><<<dim3(SEQ / GBN, SEQ / GBM, BATCH), 256, GSMEM>>>(
        qkvhi, nullptr, DM3, qkvhi + DM, DM3, DM,
        scores, nullptr, nullptr, SEQ,
        (size_t)SEQ * DM3, (size_t)SEQ * DM3, (size_t)SEQ * SEQ, scale);

    // 4) causal softmax (valid prefix only) -> fp16 P-hi
    softmax_kernel<<<BATCH * SEQ, 256>>>(scores, phi);

    // 5) att = P @ V (1-pass, K truncated causally) -> split-fp16 hi+lo
    gemm_mma_kernel<1,0,0,1><<<dim3(DM / GBN, SEQ / GBM, BATCH), 256, GSMEM>>>(
        phi, nullptr, SEQ, vthi, SEQ, SEQ,
        nullptr, atthi, attlo, DM,
        (size_t)SEQ * SEQ, (size_t)DM * SEQ, (size_t)SEQ * DM, 1.0f);

    // 6) out = att @ w_proj^T (2-pass) -> fp32
    gemm_mma_kernel<0,1,0,0><<<dim3(DM / GBN, (BATCH * SEQ) / GBM, 1), 256, GSMEM>>>(
        atthi, attlo, DM, wphi, DM, DM,
        out, nullptr, nullptr, DM, 0, 0, 0, 1.0f);
}

// round 15
// speedup vs baseline: 5.8873x; 1.1505x over previous
#include <cuda_runtime.h>
#include <cuda_fp16.h>
#include <cstdint>
#include <math.h>

// Problem constants (B=4, T=4096, C=512)
#define BATCH 4
#define SEQ   4096
#define DM    512
#define DM3   1536

// ---------------------------------------------------------------------------
// Scratch (device globals; no allocation allowed)
// ---------------------------------------------------------------------------
#define NX   ((size_t)BATCH * SEQ * DM)
#define NQKV ((size_t)BATCH * SEQ * DM3)
#define NS   ((size_t)BATCH * SEQ * SEQ)

__device__ __half g_xhi[NX];
__device__ __half g_wqhi[(size_t)DM3 * DM];
__device__ __half g_wphi[(size_t)DM * DM];
__device__ __half g_qkvhi[NQKV];
__device__ float  g_scores[NS];
__device__ __half g_phi[NS];
__device__ __half g_vthi[NX];
__device__ __half g_atthi[NX], g_attlo[NX];

// ---------------------------------------------------------------------------
// PTX helpers
// ---------------------------------------------------------------------------
__device__ __forceinline__ uint32_t smem_to_u32(const void* p) {
    uint32_t a;
    asm("{ .reg .u64 t; cvta.to.shared.u64 t, %1; cvt.u32.u64 %0, t; }"
        : "=r"(a) : "l"(p));
    return a;
}
#define CP_ASYNC16(dst, src) \
    asm volatile("cp.async.cg.shared.global [%0], [%1], 16;" :: "r"(dst), "l"(src))
#define CP_COMMIT() asm volatile("cp.async.commit_group;" ::: "memory")
#define CP_WAIT(n)  asm volatile("cp.async.wait_group %0;" :: "n"(n) : "memory")

#define LDSM_X4(r0, r1, r2, r3, addr) \
    asm volatile("ldmatrix.sync.aligned.m8n8.x4.shared.b16 {%0,%1,%2,%3}, [%4];" \
        : "=r"(r0), "=r"(r1), "=r"(r2), "=r"(r3) : "r"(addr))

__device__ __forceinline__ void mma16816(float* c,
        uint32_t a0, uint32_t a1, uint32_t a2, uint32_t a3,
        uint32_t b0, uint32_t b1) {
    asm volatile(
        "mma.sync.aligned.m16n8k16.row.col.f32.f16.f16.f32 "
        "{%0,%1,%2,%3}, {%4,%5,%6,%7}, {%8,%9}, {%0,%1,%2,%3};"
        : "+f"(c[0]), "+f"(c[1]), "+f"(c[2]), "+f"(c[3])
        : "r"(a0), "r"(a1), "r"(a2), "r"(a3), "r"(b0), "r"(b1));
}

__device__ __forceinline__ void split_f32(float v, __half& h, __half& l) {
    h = __float2half_rn(v);
    l = __float2half_rn(v - __half2float(h));
}

// ---------------------------------------------------------------------------
// fp32 -> fp16 hi (lo optional)
// ---------------------------------------------------------------------------
__global__ __launch_bounds__(256)
void split_kernel(const float* __restrict__ in, __half* __restrict__ hi,
                  __half* __restrict__ lo, int n4)
{
    int i = blockIdx.x * 256 + threadIdx.x;
    if (i >= n4) return;
    float4 v = reinterpret_cast<const float4*>(in)[i];
    float a[4] = {v.x, v.y, v.z, v.w};
    union { __half h[4]; uint2 u; } H, L;
#pragma unroll
    for (int j = 0; j < 4; j++) split_f32(a[j], H.h[j], L.h[j]);
    reinterpret_cast<uint2*>(hi)[i] = H.u;
    if (lo) reinterpret_cast<uint2*>(lo)[i] = L.u;
}

// ---------------------------------------------------------------------------
// Transpose V-hi slice of qkv: vt[b][c][s] = qkvhi[b*SEQ + s][2*DM + c]
// ---------------------------------------------------------------------------
__global__ __launch_bounds__(256)
void transpose_v_kernel(const __half* __restrict__ qhi,
                        __half* __restrict__ vthi)
{
    __shared__ __half t[32][33];
    const int b  = blockIdx.z;
    const int s0 = blockIdx.x * 32;
    const int c0 = blockIdx.y * 32;
    const int tx = threadIdx.x & 31;
    const int ty = threadIdx.x >> 5;
#pragma unroll
    for (int j = 0; j < 4; j++) {
        int s = s0 + ty + 8 * j;
        t[ty + 8 * j][tx] = qhi[((size_t)b * SEQ + s) * DM3 + 2 * DM + c0 + tx];
    }
    __syncthreads();
#pragma unroll
    for (int j = 0; j < 4; j++) {
        int c = c0 + ty + 8 * j;
        vthi[(size_t)b * DM * SEQ + (size_t)c * SEQ + s0 + tx] = t[tx][ty + 8 * j];
    }
}

// ---------------------------------------------------------------------------
// Causal softmax over valid prefix only -> fp16 P-hi (+zeros to tile end)
// ---------------------------------------------------------------------------
__global__ __launch_bounds__(256)
void softmax_kernel(const float* __restrict__ S, __half* __restrict__ phi)
{
    __shared__ float e[SEQ];
    __shared__ float redm[8], reds[8];
    const size_t row = blockIdx.x;
    const int t = (int)(row & (SEQ - 1));
    const int nval = t + 1;
    const int tile_end = ((t >> 7) + 1) << 7;
    const float* p = S + row * (size_t)SEQ;
    const int tid = threadIdx.x;

    float m = -INFINITY;
    for (int i = tid; i < nval; i += 256) m = fmaxf(m, p[i]);
#pragma unroll
    for (int o = 16; o > 0; o >>= 1)
        m = fmaxf(m, __shfl_xor_sync(0xffffffffu, m, o));
    if ((tid & 31) == 0) redm[tid >> 5] = m;
    __syncthreads();
    m = fmaxf(fmaxf(fmaxf(redm[0], redm[1]), fmaxf(redm[2], redm[3])),
              fmaxf(fmaxf(redm[4], redm[5]), fmaxf(redm[6], redm[7])));

    float s = 0.0f;
    for (int i = tid; i < nval; i += 256) {
        float ev = __expf(p[i] - m);
        e[i] = ev;
        s += ev;
    }
#pragma unroll
    for (int o = 16; o > 0; o >>= 1)
        s += __shfl_xor_sync(0xffffffffu, s, o);
    if ((tid & 31) == 0) reds[tid >> 5] = s;
    __syncthreads();
    s = reds[0] + reds[1] + reds[2] + reds[3] +
        reds[4] + reds[5] + reds[6] + reds[7];

    const float inv = 1.0f / s;
    for (int i = tid; i < tile_end; i += 256) {
        float w = (i < nval) ? e[i] * inv : 0.0f;
        phi[row * (size_t)SEQ + i] = __float2half_rn(w);
    }
}

// ---------------------------------------------------------------------------
// Warp-MMA fp16 GEMM, 3-stage cp.async pipeline, 1 sync per K-chunk.
// TWO_PASS=1: C = (Ahi+Alo)*Bhi^T; TWO_PASS=0: C = Ahi*Bhi^T.
// OUT: 0 -> fp32*scale, 1 -> split-fp16 (hi+lo), 2 -> fp16 hi only.
// KC: K-chunk size (32 or 64). CTA 128x128, 8 warps (32x64 each).
// CAUSAL_SKIP: skip tiles above diagonal.  KTRUNC: K stops at m0+128 (PV).
// ---------------------------------------------------------------------------
#define GBM 128
#define GBN 128
#define NSTAGE 3

template <int KC>
__device__ __forceinline__ void cp_tile(uint32_t sbase,
        const __half* __restrict__ g, int ld, int row0, int k0, int tid)
{
    constexpr int SKP = KC + 8;          // padded row stride (elems)
    constexpr int CPR = KC / 8;          // 16B chunks per row
#pragma unroll
    for (int it = 0; it < (128 * CPR) / 256; ++it) {
        int v = it * 256 + tid;
        int r = v / CPR;
        int c8 = (v % CPR) * 8;
        uint32_t dst = sbase + (uint32_t)(r * (SKP * 2) + c8 * 2);
        const void* src = g + (size_t)(row0 + r) * ld + k0 + c8;
        CP_ASYNC16(dst, src);
    }
}

template <int OUT, int TWO_PASS, int CAUSAL_SKIP, int KTRUNC, int KC>
__global__ __launch_bounds__(256, 2)
void gemm_mma_kernel(const __half* __restrict__ Ahi_,
                     const __half* __restrict__ Alo_, int lda,
                     const __half* __restrict__ Bhi_, int ldb,
                     int K,
                     float* __restrict__ outF_,
                     __half* __restrict__ outHi_,
                     __half* __restrict__ outLo_, int ldc,
                     size_t sA, size_t sB, size_t sC, float scale)
{
    constexpr int SKP   = KC + 8;
    constexpr int TILEB = 128 * SKP * 2;
    constexpr int A_HI  = 0;
    constexpr int A_LO  = TILEB;                       // only if TWO_PASS
    constexpr int B_HI  = (TWO_PASS ? 2 : 1) * TILEB;
    constexpr int BUFB  = (TWO_PASS ? 3 : 2) * TILEB;

    const int m0 = blockIdx.y * GBM;
    const int n0 = blockIdx.x * GBN;
    if (CAUSAL_SKIP && n0 > m0) return;

    extern __shared__ char smem[];
    const uint32_t sb = smem_to_u32(smem);
    const int tid = threadIdx.x;
    const int w    = tid >> 5;
    const int lane = tid & 31;
    const int group = lane >> 2;
    const int tig   = lane & 3;
    const int wr = w >> 1;                // 0..3 (M)
    const int wc = w & 1;                 // 0..1 (N)
    const int b  = blockIdx.z;

    const __half* Ahi = Ahi_ + (size_t)b * sA;
    const __half* Alo = TWO_PASS ? (Alo_ + (size_t)b * sA) : nullptr;
    const __half* Bhi = Bhi_ + (size_t)b * sB;

    const int K_eff = KTRUNC ? (m0 + GBM) : K;
    const int nc = K_eff / KC;            // >= 2 always

    // ldmatrix per-lane address components
    const int lq = lane >> 3;
    const int lw = lane & 7;
    const int a_r = lw + ((lq & 1) << 3);
    const int a_c = (lq & 2) << 2;
    const int b_r = lw + ((lq >> 1) << 3);
    const int b_c = (lq & 1) << 3;
    const uint32_t aoff0 = (uint32_t)((wr * 32 + a_r) * SKP + a_c) * 2;
    const uint32_t aoff1 = (uint32_t)((wr * 32 + 16 + a_r) * SKP + a_c) * 2;
    uint32_t boff[4];
#pragma unroll
    for (int ng = 0; ng < 4; ng++)
        boff[ng] = (uint32_t)((wc * 64 + ng * 16 + b_r) * SKP + b_c) * 2;

    float acc[2][8][4];
#pragma unroll
    for (int t = 0; t < 2; t++)
#pragma unroll
        for (int n = 0; n < 8; n++)
#pragma unroll
            for (int j = 0; j < 4; j++) acc[t][n][j] = 0.0f;

    // prologue: load chunks 0 and 1 into stages 0, 1
    cp_tile<KC>(sb + A_HI, Ahi, lda, m0, 0, tid);
    if (TWO_PASS) cp_tile<KC>(sb + A_LO, Alo, lda, m0, 0, tid);
    cp_tile<KC>(sb + B_HI, Bhi, ldb, n0, 0, tid);
    CP_COMMIT();
    cp_tile<KC>(sb + BUFB + A_HI, Ahi, lda, m0, KC, tid);
    if (TWO_PASS) cp_tile<KC>(sb + BUFB + A_LO, Alo, lda, m0, KC, tid);
    cp_tile<KC>(sb + BUFB + B_HI, Bhi, ldb, n0, KC, tid);
    CP_COMMIT();

    int stage = 0;
    for (int c = 0; c < nc; ++c) {
        CP_WAIT(1);                 // chunk c complete (c+1 may be in flight)
        __syncthreads();            // everyone done reading stage of c-1

        if (c + 2 < nc) {           // prefetch chunk c+2 into the freed stage
            int ps = stage + 2; if (ps >= NSTAGE) ps -= NSTAGE;
            uint32_t buf = sb + ps * BUFB;
            const int k0 = (c + 2) * KC;
            cp_tile<KC>(buf + A_HI, Ahi, lda, m0, k0, tid);
            if (TWO_PASS) cp_tile<KC>(buf + A_LO, Alo, lda, m0, k0, tid);
            cp_tile<KC>(buf + B_HI, Bhi, ldb, n0, k0, tid);
        }
        CP_COMMIT();                // commit every iteration (may be empty)

        const uint32_t buf = sb + stage * BUFB;
#pragma unroll
        for (int kk = 0; kk < KC; kk += 16) {
            const uint32_t kb = (uint32_t)kk * 2;
            uint32_t ah[2][4], bb[8][2];

            LDSM_X4(ah[0][0], ah[0][1], ah[0][2], ah[0][3], buf + A_HI + aoff0 + kb);
            LDSM_X4(ah[1][0], ah[1][1], ah[1][2], ah[1][3], buf + A_HI + aoff1 + kb);
#pragma unroll
            for (int ng = 0; ng < 4; ng++)
                LDSM_X4(bb[2 * ng][0], bb[2 * ng][1], bb[2 * ng + 1][0], bb[2 * ng + 1][1],
                        buf + B_HI + boff[ng] + kb);

            // pass 1: Ahi * Bhi
#pragma unroll
            for (int t = 0; t < 2; t++)
#pragma unroll
                for (int n = 0; n < 8; n++)
                    mma16816(acc[t][n], ah[t][0], ah[t][1], ah[t][2], ah[t][3],
                             bb[n][0], bb[n][1]);
            // pass 2: Alo * Bhi (only when TWO_PASS)
            if (TWO_PASS) {
                uint32_t ax[2][4];
                LDSM_X4(ax[0][0], ax[0][1], ax[0][2], ax[0][3], buf + A_LO + aoff0 + kb);
                LDSM_X4(ax[1][0], ax[1][1], ax[1][2], ax[1][3], buf + A_LO + aoff1 + kb);
#pragma unroll
                for (int t = 0; t < 2; t++)
#pragma unroll
                    for (int n = 0; n < 8; n++)
                        mma16816(acc[t][n], ax[t][0], ax[t][1], ax[t][2], ax[t][3],
                                 bb[n][0], bb[n][1]);
            }
        }
        if (++stage >= NSTAGE) stage = 0;
    }

    // Epilogue
#pragma unroll
    for (int t = 0; t < 2; t++) {
        const int row = m0 + wr * 32 + t * 16 + group;
#pragma unroll
        for (int n = 0; n < 8; n++) {
            const int col = n0 + wc * 64 + n * 8 + tig * 2;
            if (OUT == 0) {
                float* dst = outF_ + (size_t)b * sC;
                float2 v0 = make_float2(acc[t][n][0] * scale, acc[t][n][1] * scale);
                float2 v1 = make_float2(acc[t][n][2] * scale, acc[t][n][3] * scale);
                *reinterpret_cast<float2*>(dst + (size_t)row * ldc + col) = v0;
                *reinterpret_cast<float2*>(dst + (size_t)(row + 8) * ldc + col) = v1;
            } else if (OUT == 1) {
                __half* dh = outHi_ + (size_t)b * sC;
                __half* dl = outLo_ + (size_t)b * sC;
#pragma unroll
                for (int hh = 0; hh < 2; hh++) {
                    const int r = row + hh * 8;
                    union { __half x[2]; uint32_t u; } H, L;
                    split_f32(acc[t][n][hh * 2 + 0], H.x[0], L.x[0]);
                    split_f32(acc[t][n][hh * 2 + 1], H.x[1], L.x[1]);
                    *reinterpret_cast<uint32_t*>(dh + (size_t)r * ldc + col) = H.u;
                    *reinterpret_cast<uint32_t*>(dl + (size_t)r * ldc + col) = L.u;
                }
            } else {   // OUT == 2: hi only
                __half* dh = outHi_ + (size_t)b * sC;
#pragma unroll
                for (int hh = 0; hh < 2; hh++) {
                    const int r = row + hh * 8;
                    union { __half x[2]; uint32_t u; } H;
                    H.x[0] = __float2half_rn(acc[t][n][hh * 2 + 0]);
                    H.x[1] = __float2half_rn(acc[t][n][hh * 2 + 1]);
                    *reinterpret_cast<uint32_t*>(dh + (size_t)r * ldc + col) = H.u;
                }
            }
        }
    }
}

// smem sizes per config
#define GSMEM_1P64 (NSTAGE * 2 * (128 * (64 + 8) * 2))   // 110592
#define GSMEM_2P32 (NSTAGE * 3 * (128 * (32 + 8) * 2))   // 92160

// ---------------------------------------------------------------------------
extern "C" void kernel_launch(void* const* d_in, const int* in_sizes, int n_in,
                              void* d_out, int out_size)
{
    const float* x      = (const float*)d_in[0];   // [B,T,C]
    const float* w_qkv  = (const float*)d_in[1];   // [3C,C]
    const float* w_proj = (const float*)d_in[2];   // [C,C]
    float* out = (float*)d_out;                    // [B,T,C]

    __half *xhi, *wqhi, *wphi;
    __half *qkvhi, *phi, *vthi, *atthi, *attlo;
    float* scores;
    cudaGetSymbolAddress((void**)&xhi, g_xhi);
    cudaGetSymbolAddress((void**)&wqhi, g_wqhi);   cudaGetSymbolAddress((void**)&wphi, g_wphi);
    cudaGetSymbolAddress((void**)&qkvhi, g_qkvhi);
    cudaGetSymbolAddress((void**)&scores, g_scores);
    cudaGetSymbolAddress((void**)&phi, g_phi);
    cudaGetSymbolAddress((void**)&vthi, g_vthi);
    cudaGetSymbolAddress((void**)&atthi, g_atthi); cudaGetSymbolAddress((void**)&attlo, g_attlo);

    cudaFuncSetAttribute(gemm_mma_kernel<2,0,0,0,64>, cudaFuncAttributeMaxDynamicSharedMemorySize, GSMEM_1P64);
    cudaFuncSetAttribute(gemm_mma_kernel<0,0,1,0,64>, cudaFuncAttributeMaxDynamicSharedMemorySize, GSMEM_1P64);
    cudaFuncSetAttribute(gemm_mma_kernel<1,0,0,1,64>, cudaFuncAttributeMaxDynamicSharedMemorySize, GSMEM_1P64);
    cudaFuncSetAttribute(gemm_mma_kernel<0,1,0,0,32>, cudaFuncAttributeMaxDynamicSharedMemorySize, GSMEM_2P32);

    const float scale = 1.0f / sqrtf((float)DM);

    // 0) fp32 -> fp16 hi (x, weights; no lo needed anywhere upstream)
    {
        int n4 = (int)(NX / 4);
        split_kernel<<<(n4 + 255) / 256, 256>>>(x, xhi, nullptr, n4);
        int w4 = DM3 * DM / 4;
        split_kernel<<<(w4 + 255) / 256, 256>>>(w_qkv, wqhi, nullptr, w4);
        int p4 = DM * DM / 4;
        split_kernel<<<(p4 + 255) / 256, 256>>>(w_proj, wphi, nullptr, p4);
    }

    // 1) qkv = x @ w_qkv^T (1-pass) -> fp16 hi only
    gemm_mma_kernel<2,0,0,0,64><<<dim3(DM3 / GBN, (BATCH * SEQ) / GBM, 1), 256, GSMEM_1P64>>>(
        xhi, nullptr, DM, wqhi, DM, DM,
        nullptr, qkvhi, nullptr, DM3, 0, 0, 0, 1.0f);

    // 2) transpose V-hi: vt[b][c][s]
    transpose_v_kernel<<<dim3(SEQ / 32, DM / 32, BATCH), 256>>>(qkvhi, vthi);

    // 3) scores = (Qhi @ Khi^T) * scale (1-pass) -> fp32, lower tiles only
    gemm_mma_kernel<0,0,1,0,64><<<dim3(SEQ / GBN, SEQ / GBM, BATCH), 256, GSMEM_1P64>>>(
        qkvhi, nullptr, DM3, qkvhi + DM, DM3, DM,
        scores, nullptr, nullptr, SEQ,
        (size_t)SEQ * DM3, (size_t)SEQ * DM3, (size_t)SEQ * SEQ, scale);

    // 4) causal softmax (valid prefix only) -> fp16 P-hi
    softmax_kernel<<<BATCH * SEQ, 256>>>(scores, phi);

    // 5) att = P @ V (1-pass, K truncated causally) -> split-fp16 hi+lo
    gemm_mma_kernel<1,0,0,1,64><<<dim3(DM / GBN, SEQ / GBM, BATCH), 256, GSMEM_1P64>>>(
        phi, nullptr, SEQ, vthi, SEQ, SEQ,
        nullptr, atthi, attlo, DM,
        (size_t)SEQ * SEQ, (size_t)DM * SEQ, (size_t)SEQ * DM, 1.0f);

    // 6) out = att @ w_proj^T (2-pass) -> fp32
    gemm_mma_kernel<0,1,0,0,32><<<dim3(DM / GBN, (BATCH * SEQ) / GBM, 1), 256, GSMEM_2P32>>>(
        atthi, attlo, DM, wphi, DM, DM,
        out, nullptr, nullptr, DM, 0, 0, 0, 1.0f);
}